// round 1
// baseline (speedup 1.0000x reference)
#include <cuda_runtime.h>
#include <math.h>
#include <math_constants.h>

// Problem constants
#define BSZ 2
#define TSEQ 2048
#define CDIM 1024
#define NHEAD 16
#define DHEAD 64
#define MROWS (BSZ * TSEQ)          // 4096
#define QKVCOLS (3 * CDIM)          // 3072

// ---------------------------------------------------------------------------
// Scratch (no allocations allowed -> __device__ globals)
// ---------------------------------------------------------------------------
__device__ float g_qkv[(size_t)MROWS * QKVCOLS];                 // [4096, 3072]
__device__ float g_q[(size_t)BSZ * NHEAD * TSEQ * DHEAD];        // [B,H,T,D]
__device__ float g_k[(size_t)BSZ * NHEAD * TSEQ * DHEAD];
__device__ float g_v[(size_t)BSZ * NHEAD * TSEQ * DHEAD];
__device__ float g_y[(size_t)MROWS * CDIM];                      // [B,T,C] attn out
__device__ float2 g_rope[TSEQ * (DHEAD / 2)];                    // cos/sin table

// ---------------------------------------------------------------------------
// RoPE cos/sin table: angle computed in double for accuracy
// ---------------------------------------------------------------------------
__global__ void build_rope_kernel(float2* __restrict__ table) {
    int i = blockIdx.x * blockDim.x + threadIdx.x;
    if (i >= TSEQ * 32) return;
    int t = i >> 5;
    int j = i & 31;
    double inv = pow(10000.0, -(double)j / 32.0);
    double ang = (double)t * inv;
    table[i] = make_float2((float)cos(ang), (float)sin(ang));
}

// ---------------------------------------------------------------------------
// SGEMM: C[M,N] = A[M,K] @ B[K,N] + bias[N]
// 128x128 block tile, BK=8, 256 threads, 8x8 per-thread microtile,
// register-prefetch double buffering.
// Requires M%128==0, N%128==0, K%8==0 (true for all our shapes).
// ---------------------------------------------------------------------------
#define GBM 128
#define GBN 128
#define GBK 8

__global__ __launch_bounds__(256, 2)
void sgemm_bias_kernel(const float* __restrict__ A, const float* __restrict__ B,
                       const float* __restrict__ bias, float* __restrict__ C,
                       int M, int N, int K) {
    __shared__ float As[GBK][GBM];
    __shared__ float Bs[GBK][GBN];

    int tid = threadIdx.x;
    int row0 = blockIdx.y * GBM;
    int col0 = blockIdx.x * GBN;

    // A tile load map: 128 rows x 8 cols, one float4 per thread
    int ar = tid >> 1;
    int ac = (tid & 1) * 4;
    // B tile load map: 8 rows x 128 cols, one float4 per thread
    int br = tid >> 5;
    int bc = (tid & 31) * 4;

    int ty = tid >> 4;   // 0..15
    int tx = tid & 15;   // 0..15

    const float* Aptr = A + (size_t)(row0 + ar) * K + ac;
    const float* Bptr = B + (size_t)br * N + col0 + bc;

    float acc[8][8];
#pragma unroll
    for (int i = 0; i < 8; i++)
#pragma unroll
        for (int j = 0; j < 8; j++) acc[i][j] = 0.0f;

    int nT = K / GBK;
    float4 a0 = *(const float4*)Aptr;
    float4 b0 = *(const float4*)Bptr;

    for (int t = 0; t < nT; t++) {
        As[ac + 0][ar] = a0.x;
        As[ac + 1][ar] = a0.y;
        As[ac + 2][ar] = a0.z;
        As[ac + 3][ar] = a0.w;
        *(float4*)&Bs[br][bc] = b0;
        __syncthreads();

        if (t + 1 < nT) {
            a0 = *(const float4*)(Aptr + (size_t)(t + 1) * GBK);
            b0 = *(const float4*)(Bptr + (size_t)(t + 1) * GBK * N);
        }

#pragma unroll
        for (int k = 0; k < GBK; k++) {
            float ra[8], rb[8];
            *(float4*)&ra[0] = *(const float4*)&As[k][ty * 8];
            *(float4*)&ra[4] = *(const float4*)&As[k][ty * 8 + 4];
            *(float4*)&rb[0] = *(const float4*)&Bs[k][tx * 8];
            *(float4*)&rb[4] = *(const float4*)&Bs[k][tx * 8 + 4];
#pragma unroll
            for (int i = 0; i < 8; i++)
#pragma unroll
                for (int j = 0; j < 8; j++)
                    acc[i][j] += ra[i] * rb[j];
        }
        __syncthreads();
    }

    // Epilogue: add bias, vectorized store
    float rbias[8];
#pragma unroll
    for (int j = 0; j < 8; j++) rbias[j] = bias[col0 + tx * 8 + j];

#pragma unroll
    for (int i = 0; i < 8; i++) {
        size_t row = (size_t)(row0 + ty * 8 + i);
        float* Cp = C + row * N + col0 + tx * 8;
        float4 v0, v1;
        v0.x = acc[i][0] + rbias[0];
        v0.y = acc[i][1] + rbias[1];
        v0.z = acc[i][2] + rbias[2];
        v0.w = acc[i][3] + rbias[3];
        v1.x = acc[i][4] + rbias[4];
        v1.y = acc[i][5] + rbias[5];
        v1.z = acc[i][6] + rbias[6];
        v1.w = acc[i][7] + rbias[7];
        *(float4*)Cp = v0;
        *(float4*)(Cp + 4) = v1;
    }
}

// ---------------------------------------------------------------------------
// RoPE + head scatter: qkv [B,T,3C] -> q,k (roped), v at [B,H,T,D]
// ---------------------------------------------------------------------------
__global__ void rope_scatter_kernel(const float* __restrict__ qkv,
                                    const float2* __restrict__ rope,
                                    float* __restrict__ q, float* __restrict__ k,
                                    float* __restrict__ v) {
    int idx = blockIdx.x * blockDim.x + threadIdx.x;  // over B*T*C = 4.19M
    int d = idx & 63;
    int h = (idx >> 6) & 15;
    int t = (idx >> 10) & 2047;
    int b = idx >> 21;

    size_t base = (size_t)(b * TSEQ + t) * QKVCOLS + h * DHEAD;
    float2 cs = rope[t * 32 + (d & 31)];

    float qv = qkv[base + d];
    float kv = qkv[base + CDIM + d];
    float vv = qkv[base + 2 * CDIM + d];

    int dp = (d < 32) ? d + 32 : d - 32;
    float sgn = (d < 32) ? -1.0f : 1.0f;
    float qr = qkv[base + dp];
    float kr = qkv[base + CDIM + dp];

    size_t o = ((size_t)(b * NHEAD + h) * TSEQ + t) * DHEAD + d;
    q[o] = qv * cs.x + sgn * qr * cs.y;
    k[o] = kv * cs.x + sgn * kr * cs.y;
    v[o] = vv;
}

// ---------------------------------------------------------------------------
// Flash attention (fp32, causal): Br=Bc=64, D=64, 256 threads (16x16, 4x4 each)
// Output written directly in [B,T,H*D] layout for the projection GEMM.
// ---------------------------------------------------------------------------
__global__ __launch_bounds__(256, 4)
void flash_attn_kernel(const float* __restrict__ Q, const float* __restrict__ K,
                       const float* __restrict__ V, float* __restrict__ Y) {
    __shared__ float Qs[64][64];
    __shared__ float KPs[64][64];   // K tile, reused as P tile
    __shared__ float Vs[64][64];

    int bh = blockIdx.y;                         // 0..31
    int qt = gridDim.x - 1 - blockIdx.x;         // heavy tiles launch first
    int q0 = qt * 64;

    const float* Qb = Q + ((size_t)bh * TSEQ + q0) * DHEAD;
    const float* Kb = K + (size_t)bh * TSEQ * DHEAD;
    const float* Vb = V + (size_t)bh * TSEQ * DHEAD;

    int tid = threadIdx.x;
    int ty = tid >> 4;   // row group
    int tx = tid & 15;   // col group

    // Load Q tile (64x64 = 1024 float4)
    for (int i = tid; i < 64 * 64 / 4; i += 256)
        ((float4*)&Qs[0][0])[i] = ((const float4*)Qb)[i];

    float m[4], l[4], acc[4][4];
#pragma unroll
    for (int i = 0; i < 4; i++) {
        m[i] = -CUDART_INF_F;
        l[i] = 0.0f;
#pragma unroll
        for (int j = 0; j < 4; j++) acc[i][j] = 0.0f;
    }

    const float scale = 0.125f;  // 1/sqrt(64)
    int nkt = qt + 1;

    for (int jt = 0; jt < nkt; jt++) {
        int k0 = jt * 64;
        __syncthreads();  // prior-iter P/V reads done (also covers Q load, iter 0)
        for (int i = tid; i < 64 * 64 / 4; i += 256) {
            ((float4*)&KPs[0][0])[i] = ((const float4*)(Kb + (size_t)k0 * DHEAD))[i];
            ((float4*)&Vs[0][0])[i]  = ((const float4*)(Vb + (size_t)k0 * DHEAD))[i];
        }
        __syncthreads();

        // S = Q K^T
        float S[4][4];
#pragma unroll
        for (int i = 0; i < 4; i++)
#pragma unroll
            for (int j = 0; j < 4; j++) S[i][j] = 0.0f;

#pragma unroll 4
        for (int d4 = 0; d4 < DHEAD; d4 += 4) {
            float4 qv[4], kv[4];
#pragma unroll
            for (int i = 0; i < 4; i++) qv[i] = *(const float4*)&Qs[ty * 4 + i][d4];
#pragma unroll
            for (int j = 0; j < 4; j++) kv[j] = *(const float4*)&KPs[tx * 4 + j][d4];
#pragma unroll
            for (int i = 0; i < 4; i++)
#pragma unroll
                for (int j = 0; j < 4; j++) {
                    S[i][j] += qv[i].x * kv[j].x;
                    S[i][j] += qv[i].y * kv[j].y;
                    S[i][j] += qv[i].z * kv[j].z;
                    S[i][j] += qv[i].w * kv[j].w;
                }
        }

        // Causal mask + scale
#pragma unroll
        for (int i = 0; i < 4; i++) {
            int gr = q0 + ty * 4 + i;
#pragma unroll
            for (int j = 0; j < 4; j++) {
                int gc = k0 + tx * 4 + j;
                S[i][j] = (gc <= gr) ? S[i][j] * scale : -CUDART_INF_F;
            }
        }

        // Online softmax
        float mnew[4], rs[4];
#pragma unroll
        for (int i = 0; i < 4; i++) {
            float mx = fmaxf(fmaxf(S[i][0], S[i][1]), fmaxf(S[i][2], S[i][3]));
#pragma unroll
            for (int o = 8; o >= 1; o >>= 1)
                mx = fmaxf(mx, __shfl_xor_sync(0xffffffff, mx, o, 16));
            mnew[i] = fmaxf(m[i], mx);

            float s = 0.0f;
#pragma unroll
            for (int j = 0; j < 4; j++) {
                S[i][j] = expf(S[i][j] - mnew[i]);
                s += S[i][j];
            }
#pragma unroll
            for (int o = 8; o >= 1; o >>= 1)
                s += __shfl_xor_sync(0xffffffff, s, o, 16);
            rs[i] = s;
        }

#pragma unroll
        for (int i = 0; i < 4; i++) {
            float corr = expf(m[i] - mnew[i]);   // exp(-inf)=0 on first tile
            l[i] = l[i] * corr + rs[i];
            m[i] = mnew[i];
#pragma unroll
            for (int j = 0; j < 4; j++) acc[i][j] *= corr;
        }

        __syncthreads();  // everyone done reading KPs as K
        // Store P into KPs[r][c]
#pragma unroll
        for (int i = 0; i < 4; i++)
            *(float4*)&KPs[ty * 4 + i][tx * 4] =
                make_float4(S[i][0], S[i][1], S[i][2], S[i][3]);
        __syncthreads();

        // O += P @ V  (rows ty*4.., dout columns tx*4..)
#pragma unroll 8
        for (int c = 0; c < 64; c++) {
            float4 vv = *(const float4*)&Vs[c][tx * 4];
#pragma unroll
            for (int i = 0; i < 4; i++) {
                float pv = KPs[ty * 4 + i][c];
                acc[i][0] += pv * vv.x;
                acc[i][1] += pv * vv.y;
                acc[i][2] += pv * vv.z;
                acc[i][3] += pv * vv.w;
            }
        }
    }

    // Normalize and write to [B, T, H*D]
    int b = bh >> 4;
    int h = bh & 15;
#pragma unroll
    for (int i = 0; i < 4; i++) {
        int t = q0 + ty * 4 + i;
        float inv = 1.0f / l[i];
        float4 o4 = make_float4(acc[i][0] * inv, acc[i][1] * inv,
                                acc[i][2] * inv, acc[i][3] * inv);
        *(float4*)&Y[((size_t)(b * TSEQ + t) * CDIM) + h * DHEAD + tx * 4] = o4;
    }
}

// ---------------------------------------------------------------------------
// Launch
// ---------------------------------------------------------------------------
extern "C" void kernel_launch(void* const* d_in, const int* in_sizes, int n_in,
                              void* d_out, int out_size) {
    const float* x      = (const float*)d_in[0];
    const float* w_attn = (const float*)d_in[1];
    const float* b_attn = (const float*)d_in[2];
    const float* w_proj = (const float*)d_in[3];
    const float* b_proj = (const float*)d_in[4];
    float* out = (float*)d_out;

    float *qkv, *q, *k, *v, *y;
    float2* rope;
    cudaGetSymbolAddress((void**)&qkv, g_qkv);
    cudaGetSymbolAddress((void**)&q, g_q);
    cudaGetSymbolAddress((void**)&k, g_k);
    cudaGetSymbolAddress((void**)&v, g_v);
    cudaGetSymbolAddress((void**)&y, g_y);
    cudaGetSymbolAddress((void**)&rope, g_rope);

    // 1) RoPE table (cheap, deterministic)
    build_rope_kernel<<<(TSEQ * 32 + 255) / 256, 256>>>(rope);

    // 2) QKV GEMM: [4096,1024] @ [1024,3072] + b_attn
    sgemm_bias_kernel<<<dim3(QKVCOLS / GBN, MROWS / GBM), 256>>>(
        x, w_attn, b_attn, qkv, MROWS, QKVCOLS, CDIM);

    // 3) RoPE + scatter to [B,H,T,D]
    rope_scatter_kernel<<<(BSZ * TSEQ * CDIM) / 256, 256>>>(qkv, rope, q, k, v);

    // 4) Flash attention (causal), output directly in [B,T,C]
    flash_attn_kernel<<<dim3(TSEQ / 64, BSZ * NHEAD), 256>>>(q, k, v, y);

    // 5) Output projection: [4096,1024] @ [1024,1024] + b_proj
    sgemm_bias_kernel<<<dim3(CDIM / GBN, MROWS / GBM), 256>>>(
        y, w_proj, b_proj, out, MROWS, CDIM, CDIM);
}

// round 2
// speedup vs baseline: 2.5998x; 2.5998x over previous
#include <cuda_runtime.h>
#include <math.h>
#include <math_constants.h>
#include <stdint.h>

// Problem constants
#define BSZ 2
#define TSEQ 2048
#define CDIM 1024
#define NHEAD 16
#define DHEAD 64
#define MROWS (BSZ * TSEQ)          // 4096
#define QKVCOLS (3 * CDIM)          // 3072

// ---------------------------------------------------------------------------
// Scratch
// ---------------------------------------------------------------------------
__device__ float g_qkv[(size_t)MROWS * QKVCOLS];
__device__ float g_q[(size_t)BSZ * NHEAD * TSEQ * DHEAD];
__device__ float g_k[(size_t)BSZ * NHEAD * TSEQ * DHEAD];
__device__ float g_v[(size_t)BSZ * NHEAD * TSEQ * DHEAD];
__device__ float g_y[(size_t)MROWS * CDIM];
__device__ float2 g_rope[TSEQ * (DHEAD / 2)];

// ---------------------------------------------------------------------------
// RoPE table
// ---------------------------------------------------------------------------
__global__ void build_rope_kernel(float2* __restrict__ table) {
    int i = blockIdx.x * blockDim.x + threadIdx.x;
    if (i >= TSEQ * 32) return;
    int t = i >> 5;
    int j = i & 31;
    double inv = pow(10000.0, -(double)j / 32.0);
    double ang = (double)t * inv;
    table[i] = make_float2((float)cos(ang), (float)sin(ang));
}

// ---------------------------------------------------------------------------
// tf32 helpers
// ---------------------------------------------------------------------------
__device__ __forceinline__ uint32_t f2tf32(float x) {
    uint32_t r;
    asm("cvt.rna.tf32.f32 %0, %1;" : "=r"(r) : "f"(x));
    return r;
}

__device__ __forceinline__ void mma_tf32(float c[4], uint32_t a0, uint32_t a1,
                                         uint32_t a2, uint32_t a3,
                                         uint32_t b0, uint32_t b1) {
    asm volatile(
        "mma.sync.aligned.m16n8k8.row.col.f32.tf32.tf32.f32 "
        "{%0,%1,%2,%3}, {%4,%5,%6,%7}, {%8,%9}, {%0,%1,%2,%3};\n"
        : "+f"(c[0]), "+f"(c[1]), "+f"(c[2]), "+f"(c[3])
        : "r"(a0), "r"(a1), "r"(a2), "r"(a3), "r"(b0), "r"(b1));
}

// ---------------------------------------------------------------------------
// TF32 tensor-core GEMM: C[M,N] = A[M,K] @ B[K,N] + bias
// 128x128x32 CTA tile, 256 threads = 8 warps (2m x 4n), warp tile 64x32.
// A smem in mma-fragment order (conflict-free LDS.128), B smem [k][n] padded.
// ---------------------------------------------------------------------------
#define TBM 128
#define TBN 128
#define TBK 32
#define ACHUNK 132                   // 128 data floats + 4 pad per (mblk,kk) chunk
#define ASMEM (32 * ACHUNK)          // 4224 floats
#define BROWP 132                    // B row pad
#define BSMEM (TBK * BROWP)          // 4224 floats
#define GEMM_SMEM_BYTES ((ASMEM + BSMEM) * 4)

__global__ __launch_bounds__(256)
void gemm_tf32_kernel(const float* __restrict__ A, const float* __restrict__ B,
                      const float* __restrict__ bias, float* __restrict__ C,
                      int M, int N, int K) {
    extern __shared__ float sm[];
    float* As = sm;               // fragment-order
    float* Bs = sm + ASMEM;       // [k][BROWP]

    const int tid = threadIdx.x;
    const int lane = tid & 31;
    const int warp = tid >> 5;
    const int wm = warp >> 2;     // 0..1
    const int wn = warp & 3;      // 0..3
    const int row0 = blockIdx.y * TBM;
    const int col0 = blockIdx.x * TBN;

    float acc[4][4][4];
#pragma unroll
    for (int im = 0; im < 4; im++)
#pragma unroll
        for (int in = 0; in < 4; in++)
#pragma unroll
            for (int r = 0; r < 4; r++) acc[im][in][r] = 0.0f;

    // Loader maps (4 float4 each for A and B tiles)
    int arow[4], akb[4];
    const float* agp[4];
    int brow[4], bcol[4];
    const float* bgp[4];
#pragma unroll
    for (int i = 0; i < 4; i++) {
        int idx = tid + i * 256;          // 0..1023
        arow[i] = idx >> 3;               // 0..127
        akb[i] = (idx & 7) << 2;          // 0..28
        agp[i] = A + (size_t)(row0 + arow[i]) * K + akb[i];
        brow[i] = idx >> 5;               // 0..31
        bcol[i] = (idx & 31) << 2;        // 0..124
        bgp[i] = B + (size_t)brow[i] * N + col0 + bcol[i];
    }

    const int nT = K / TBK;
    float4 aR[4], bR[4];
#pragma unroll
    for (int i = 0; i < 4; i++) {
        aR[i] = *(const float4*)agp[i];
        bR[i] = *(const float4*)bgp[i];
    }

    const int l4 = lane & 3;
    const int ln4 = lane >> 2;

    for (int t = 0; t < nT; t++) {
        // ---- store tiles to smem (converted to tf32) ----
#pragma unroll
        for (int i = 0; i < 4; i++) {
            int row = arow[i];
            int chunkBase = (row >> 4) * 4;
            int laneBase = (row & 7) << 2;
            int rowbit = (row >> 3) & 1;
            float av[4] = {aR[i].x, aR[i].y, aR[i].z, aR[i].w};
#pragma unroll
            for (int j = 0; j < 4; j++) {
                int k = akb[i] + j;
                int chunk = chunkBase + (k >> 3);
                int lane_s = laneBase | (k & 3);
                int reg = (((k >> 2) & 1) << 1) | rowbit;
                As[chunk * ACHUNK + lane_s * 4 + reg] =
                    __uint_as_float(f2tf32(av[j]));
            }
            float4 bv;
            bv.x = __uint_as_float(f2tf32(bR[i].x));
            bv.y = __uint_as_float(f2tf32(bR[i].y));
            bv.z = __uint_as_float(f2tf32(bR[i].z));
            bv.w = __uint_as_float(f2tf32(bR[i].w));
            *(float4*)&Bs[brow[i] * BROWP + bcol[i]] = bv;
        }
        __syncthreads();

        // ---- prefetch next tiles ----
        if (t + 1 < nT) {
#pragma unroll
            for (int i = 0; i < 4; i++) {
                aR[i] = *(const float4*)(agp[i] + (size_t)(t + 1) * TBK);
                bR[i] = *(const float4*)(bgp[i] + (size_t)(t + 1) * TBK * N);
            }
        }

        // ---- compute: 4 k8 steps ----
#pragma unroll
        for (int kk = 0; kk < 4; kk++) {
            float4 af[4];
#pragma unroll
            for (int im = 0; im < 4; im++) {
                int mblk = wm * 4 + im;
                af[im] = *(const float4*)&As[(mblk * 4 + kk) * ACHUNK + lane * 4];
            }
            uint32_t bf[4][2];
#pragma unroll
            for (int in = 0; in < 4; in++) {
                int n = wn * 32 + in * 8 + ln4;
                bf[in][0] = __float_as_uint(Bs[(kk * 8 + l4) * BROWP + n]);
                bf[in][1] = __float_as_uint(Bs[(kk * 8 + l4 + 4) * BROWP + n]);
            }
#pragma unroll
            for (int im = 0; im < 4; im++)
#pragma unroll
                for (int in = 0; in < 4; in++)
                    mma_tf32(acc[im][in],
                             __float_as_uint(af[im].x), __float_as_uint(af[im].y),
                             __float_as_uint(af[im].z), __float_as_uint(af[im].w),
                             bf[in][0], bf[in][1]);
        }
        __syncthreads();
    }

    // ---- epilogue ----
    const int lr = lane >> 2;
    const int lc = (lane & 3) * 2;
#pragma unroll
    for (int im = 0; im < 4; im++) {
        int r = row0 + wm * 64 + im * 16 + lr;
#pragma unroll
        for (int in = 0; in < 4; in++) {
            int c = col0 + wn * 32 + in * 8 + lc;
            float b0 = bias[c], b1 = bias[c + 1];
            float2 v0 = make_float2(acc[im][in][0] + b0, acc[im][in][1] + b1);
            float2 v1 = make_float2(acc[im][in][2] + b0, acc[im][in][3] + b1);
            *(float2*)&C[(size_t)r * N + c] = v0;
            *(float2*)&C[(size_t)(r + 8) * N + c] = v1;
        }
    }
}

// ---------------------------------------------------------------------------
// RoPE + head scatter
// ---------------------------------------------------------------------------
__global__ void rope_scatter_kernel(const float* __restrict__ qkv,
                                    const float2* __restrict__ rope,
                                    float* __restrict__ q, float* __restrict__ k,
                                    float* __restrict__ v) {
    int idx = blockIdx.x * blockDim.x + threadIdx.x;
    int d = idx & 63;
    int h = (idx >> 6) & 15;
    int t = (idx >> 10) & 2047;
    int b = idx >> 21;

    size_t base = (size_t)(b * TSEQ + t) * QKVCOLS + h * DHEAD;
    float2 cs = rope[t * 32 + (d & 31)];

    float qv = qkv[base + d];
    float kv = qkv[base + CDIM + d];
    float vv = qkv[base + 2 * CDIM + d];

    int dp = (d < 32) ? d + 32 : d - 32;
    float sgn = (d < 32) ? -1.0f : 1.0f;
    float qr = qkv[base + dp];
    float kr = qkv[base + CDIM + dp];

    size_t o = ((size_t)(b * NHEAD + h) * TSEQ + t) * DHEAD + d;
    q[o] = qv * cs.x + sgn * qr * cs.y;
    k[o] = kv * cs.x + sgn * kr * cs.y;
    v[o] = vv;
}

// ---------------------------------------------------------------------------
// Flash attention (fp32, causal): 64x64 tiles, bank-conflict-free K loads,
// float4 P@V. Each thread owns S rows {ty*4+i}, S cols {tx+16j}, out cols tx*4.
// ---------------------------------------------------------------------------
#define KPPAD 68
#define FLASH_SMEM_BYTES ((64 * 64 + 64 * KPPAD + 64 * 64) * 4)

__global__ __launch_bounds__(256)
void flash_attn_kernel(const float* __restrict__ Q, const float* __restrict__ K,
                       const float* __restrict__ V, float* __restrict__ Y) {
    extern __shared__ float fsm[];
    float* Qs = fsm;                 // [64][64]
    float* KPs = fsm + 64 * 64;      // [64][KPPAD] — K tile, reused as P tile
    float* Vs = fsm + 64 * 64 + 64 * KPPAD;  // [64][64]

    int bh = blockIdx.y;
    int qt = gridDim.x - 1 - blockIdx.x;     // heavy tiles first
    int q0 = qt * 64;

    const float* Qb = Q + ((size_t)bh * TSEQ + q0) * DHEAD;
    const float* Kb = K + (size_t)bh * TSEQ * DHEAD;
    const float* Vb = V + (size_t)bh * TSEQ * DHEAD;

    int tid = threadIdx.x;
    int ty = tid >> 4;   // 0..15 (row group)
    int tx = tid & 15;   // 0..15 (col group)

    // Load Q tile
    for (int i = tid; i < 64 * 64 / 4; i += 256)
        ((float4*)Qs)[i] = ((const float4*)Qb)[i];

    float m[4], l[4], acc[4][4];
#pragma unroll
    for (int i = 0; i < 4; i++) {
        m[i] = -CUDART_INF_F;
        l[i] = 0.0f;
#pragma unroll
        for (int j = 0; j < 4; j++) acc[i][j] = 0.0f;
    }

    const float scale = 0.125f;
    int nkt = qt + 1;

    for (int jt = 0; jt < nkt; jt++) {
        int k0 = jt * 64;
        __syncthreads();
        // K tile -> KPs (padded rows), V tile -> Vs
        for (int i = tid; i < 64 * 16; i += 256) {  // 1024 float4
            int r = i >> 4;
            int c4 = (i & 15) << 2;
            *(float4*)&KPs[r * KPPAD + c4] =
                ((const float4*)(Kb + (size_t)k0 * DHEAD))[i];
            ((float4*)Vs)[i] = ((const float4*)(Vb + (size_t)k0 * DHEAD))[i];
        }
        __syncthreads();

        // S = Q K^T : rows ty*4+i, cols tx+16j
        float S[4][4];
#pragma unroll
        for (int i = 0; i < 4; i++)
#pragma unroll
            for (int j = 0; j < 4; j++) S[i][j] = 0.0f;

#pragma unroll 4
        for (int d4 = 0; d4 < DHEAD; d4 += 4) {
            float4 qv[4], kv[4];
#pragma unroll
            for (int i = 0; i < 4; i++)
                qv[i] = *(const float4*)&Qs[(ty * 4 + i) * 64 + d4];
#pragma unroll
            for (int j = 0; j < 4; j++)
                kv[j] = *(const float4*)&KPs[(tx + 16 * j) * KPPAD + d4];
#pragma unroll
            for (int i = 0; i < 4; i++)
#pragma unroll
                for (int j = 0; j < 4; j++) {
                    S[i][j] += qv[i].x * kv[j].x;
                    S[i][j] += qv[i].y * kv[j].y;
                    S[i][j] += qv[i].z * kv[j].z;
                    S[i][j] += qv[i].w * kv[j].w;
                }
        }

        // Causal mask + scale
#pragma unroll
        for (int i = 0; i < 4; i++) {
            int gr = q0 + ty * 4 + i;
#pragma unroll
            for (int j = 0; j < 4; j++) {
                int gc = k0 + tx + 16 * j;
                S[i][j] = (gc <= gr) ? S[i][j] * scale : -CUDART_INF_F;
            }
        }

        // Online softmax (reduce over 16-lane tx groups)
        float mnew[4], rs[4];
#pragma unroll
        for (int i = 0; i < 4; i++) {
            float mx = fmaxf(fmaxf(S[i][0], S[i][1]), fmaxf(S[i][2], S[i][3]));
#pragma unroll
            for (int o = 8; o >= 1; o >>= 1)
                mx = fmaxf(mx, __shfl_xor_sync(0xffffffff, mx, o, 16));
            mnew[i] = fmaxf(m[i], mx);

            float s = 0.0f;
#pragma unroll
            for (int j = 0; j < 4; j++) {
                S[i][j] = expf(S[i][j] - mnew[i]);
                s += S[i][j];
            }
#pragma unroll
            for (int o = 8; o >= 1; o >>= 1)
                s += __shfl_xor_sync(0xffffffff, s, o, 16);
            rs[i] = s;
        }

#pragma unroll
        for (int i = 0; i < 4; i++) {
            float corr = expf(m[i] - mnew[i]);
            l[i] = l[i] * corr + rs[i];
            m[i] = mnew[i];
#pragma unroll
            for (int j = 0; j < 4; j++) acc[i][j] *= corr;
        }

        __syncthreads();  // done reading KPs as K
        // Store P (scattered cols tx+16j -> conflict-free scalar stores)
#pragma unroll
        for (int i = 0; i < 4; i++)
#pragma unroll
            for (int j = 0; j < 4; j++)
                KPs[(ty * 4 + i) * KPPAD + tx + 16 * j] = S[i][j];
        __syncthreads();

        // O += P @ V, float4 both sides
#pragma unroll 4
        for (int c4 = 0; c4 < 64; c4 += 4) {
            float4 p4[4], v4[4];
#pragma unroll
            for (int i = 0; i < 4; i++)
                p4[i] = *(const float4*)&KPs[(ty * 4 + i) * KPPAD + c4];
#pragma unroll
            for (int j = 0; j < 4; j++)
                v4[j] = *(const float4*)&Vs[(c4 + j) * 64 + tx * 4];
#pragma unroll
            for (int i = 0; i < 4; i++) {
                acc[i][0] += p4[i].x * v4[0].x + p4[i].y * v4[1].x +
                             p4[i].z * v4[2].x + p4[i].w * v4[3].x;
                acc[i][1] += p4[i].x * v4[0].y + p4[i].y * v4[1].y +
                             p4[i].z * v4[2].y + p4[i].w * v4[3].y;
                acc[i][2] += p4[i].x * v4[0].z + p4[i].y * v4[1].z +
                             p4[i].z * v4[2].z + p4[i].w * v4[3].z;
                acc[i][3] += p4[i].x * v4[0].w + p4[i].y * v4[1].w +
                             p4[i].z * v4[2].w + p4[i].w * v4[3].w;
            }
        }
    }

    // Normalize and write to [B, T, H*D]
    int b = bh >> 4;
    int h = bh & 15;
#pragma unroll
    for (int i = 0; i < 4; i++) {
        int t = q0 + ty * 4 + i;
        float inv = 1.0f / l[i];
        float4 o4 = make_float4(acc[i][0] * inv, acc[i][1] * inv,
                                acc[i][2] * inv, acc[i][3] * inv);
        *(float4*)&Y[((size_t)(b * TSEQ + t) * CDIM) + h * DHEAD + tx * 4] = o4;
    }
}

// ---------------------------------------------------------------------------
// Launch
// ---------------------------------------------------------------------------
extern "C" void kernel_launch(void* const* d_in, const int* in_sizes, int n_in,
                              void* d_out, int out_size) {
    const float* x      = (const float*)d_in[0];
    const float* w_attn = (const float*)d_in[1];
    const float* b_attn = (const float*)d_in[2];
    const float* w_proj = (const float*)d_in[3];
    const float* b_proj = (const float*)d_in[4];
    float* out = (float*)d_out;

    float *qkv, *q, *k, *v, *y;
    float2* rope;
    cudaGetSymbolAddress((void**)&qkv, g_qkv);
    cudaGetSymbolAddress((void**)&q, g_q);
    cudaGetSymbolAddress((void**)&k, g_k);
    cudaGetSymbolAddress((void**)&v, g_v);
    cudaGetSymbolAddress((void**)&y, g_y);
    cudaGetSymbolAddress((void**)&rope, g_rope);

    cudaFuncSetAttribute(gemm_tf32_kernel,
                         cudaFuncAttributeMaxDynamicSharedMemorySize,
                         GEMM_SMEM_BYTES);
    cudaFuncSetAttribute(flash_attn_kernel,
                         cudaFuncAttributeMaxDynamicSharedMemorySize,
                         FLASH_SMEM_BYTES);

    build_rope_kernel<<<(TSEQ * 32 + 255) / 256, 256>>>(rope);

    // QKV GEMM: [4096,1024] @ [1024,3072] + b_attn  (tf32 tensor cores)
    gemm_tf32_kernel<<<dim3(QKVCOLS / TBN, MROWS / TBM), 256, GEMM_SMEM_BYTES>>>(
        x, w_attn, b_attn, qkv, MROWS, QKVCOLS, CDIM);

    rope_scatter_kernel<<<(BSZ * TSEQ * CDIM) / 256, 256>>>(qkv, rope, q, k, v);

    flash_attn_kernel<<<dim3(TSEQ / 64, BSZ * NHEAD), 256, FLASH_SMEM_BYTES>>>(
        q, k, v, y);

    // Output projection (tf32 tensor cores)
    gemm_tf32_kernel<<<dim3(CDIM / TBN, MROWS / TBM), 256, GEMM_SMEM_BYTES>>>(
        y, w_proj, b_proj, out, MROWS, CDIM, CDIM);
}

// round 3
// speedup vs baseline: 4.0363x; 1.5526x over previous
#include <cuda_runtime.h>
#include <math.h>
#include <math_constants.h>
#include <stdint.h>

// Problem constants
#define BSZ 2
#define TSEQ 2048
#define CDIM 1024
#define NHEAD 16
#define DHEAD 64
#define MROWS (BSZ * TSEQ)          // 4096
#define QKVCOLS (3 * CDIM)          // 3072

// ---------------------------------------------------------------------------
// Scratch
// ---------------------------------------------------------------------------
__device__ float g_qkv[(size_t)MROWS * QKVCOLS];
__device__ float g_q[(size_t)BSZ * NHEAD * TSEQ * DHEAD];
__device__ float g_k[(size_t)BSZ * NHEAD * TSEQ * DHEAD];
__device__ float g_v[(size_t)BSZ * NHEAD * TSEQ * DHEAD];
__device__ float g_y[(size_t)MROWS * CDIM];
__device__ float2 g_rope[TSEQ * (DHEAD / 2)];

// ---------------------------------------------------------------------------
// RoPE table
// ---------------------------------------------------------------------------
__global__ void build_rope_kernel(float2* __restrict__ table) {
    int i = blockIdx.x * blockDim.x + threadIdx.x;
    if (i >= TSEQ * 32) return;
    int t = i >> 5;
    int j = i & 31;
    double inv = pow(10000.0, -(double)j / 32.0);
    double ang = (double)t * inv;
    table[i] = make_float2((float)cos(ang), (float)sin(ang));
}

// ---------------------------------------------------------------------------
// tf32 / math helpers
// ---------------------------------------------------------------------------
__device__ __forceinline__ uint32_t f2tf32(float x) {
    uint32_t r;
    asm("cvt.rna.tf32.f32 %0, %1;" : "=r"(r) : "f"(x));
    return r;
}
__device__ __forceinline__ float tf32f(float x) {
    return __uint_as_float(f2tf32(x));
}
__device__ __forceinline__ float ex2f(float x) {
    float r;
    asm("ex2.approx.ftz.f32 %0, %1;" : "=f"(r) : "f"(x));
    return r;
}

__device__ __forceinline__ void mma_tf32(float c[4], uint32_t a0, uint32_t a1,
                                         uint32_t a2, uint32_t a3,
                                         uint32_t b0, uint32_t b1) {
    asm volatile(
        "mma.sync.aligned.m16n8k8.row.col.f32.tf32.tf32.f32 "
        "{%0,%1,%2,%3}, {%4,%5,%6,%7}, {%8,%9}, {%0,%1,%2,%3};\n"
        : "+f"(c[0]), "+f"(c[1]), "+f"(c[2]), "+f"(c[3])
        : "r"(a0), "r"(a1), "r"(a2), "r"(a3), "r"(b0), "r"(b1));
}

// ---------------------------------------------------------------------------
// TF32 tensor-core GEMM (unchanged from round 2)
// ---------------------------------------------------------------------------
#define TBM 128
#define TBN 128
#define TBK 32
#define ACHUNK 132
#define ASMEM (32 * ACHUNK)
#define BROWP 132
#define BSMEM (TBK * BROWP)
#define GEMM_SMEM_BYTES ((ASMEM + BSMEM) * 4)

__global__ __launch_bounds__(256)
void gemm_tf32_kernel(const float* __restrict__ A, const float* __restrict__ B,
                      const float* __restrict__ bias, float* __restrict__ C,
                      int M, int N, int K) {
    extern __shared__ float sm[];
    float* As = sm;
    float* Bs = sm + ASMEM;

    const int tid = threadIdx.x;
    const int lane = tid & 31;
    const int warp = tid >> 5;
    const int wm = warp >> 2;
    const int wn = warp & 3;
    const int row0 = blockIdx.y * TBM;
    const int col0 = blockIdx.x * TBN;

    float acc[4][4][4];
#pragma unroll
    for (int im = 0; im < 4; im++)
#pragma unroll
        for (int in = 0; in < 4; in++)
#pragma unroll
            for (int r = 0; r < 4; r++) acc[im][in][r] = 0.0f;

    int arow[4], akb[4];
    const float* agp[4];
    int brow[4], bcol[4];
    const float* bgp[4];
#pragma unroll
    for (int i = 0; i < 4; i++) {
        int idx = tid + i * 256;
        arow[i] = idx >> 3;
        akb[i] = (idx & 7) << 2;
        agp[i] = A + (size_t)(row0 + arow[i]) * K + akb[i];
        brow[i] = idx >> 5;
        bcol[i] = (idx & 31) << 2;
        bgp[i] = B + (size_t)brow[i] * N + col0 + bcol[i];
    }

    const int nT = K / TBK;
    float4 aR[4], bR[4];
#pragma unroll
    for (int i = 0; i < 4; i++) {
        aR[i] = *(const float4*)agp[i];
        bR[i] = *(const float4*)bgp[i];
    }

    const int l4 = lane & 3;
    const int ln4 = lane >> 2;

    for (int t = 0; t < nT; t++) {
#pragma unroll
        for (int i = 0; i < 4; i++) {
            int row = arow[i];
            int chunkBase = (row >> 4) * 4;
            int laneBase = (row & 7) << 2;
            int rowbit = (row >> 3) & 1;
            float av[4] = {aR[i].x, aR[i].y, aR[i].z, aR[i].w};
#pragma unroll
            for (int j = 0; j < 4; j++) {
                int k = akb[i] + j;
                int chunk = chunkBase + (k >> 3);
                int lane_s = laneBase | (k & 3);
                int reg = (((k >> 2) & 1) << 1) | rowbit;
                As[chunk * ACHUNK + lane_s * 4 + reg] =
                    __uint_as_float(f2tf32(av[j]));
            }
            float4 bv;
            bv.x = __uint_as_float(f2tf32(bR[i].x));
            bv.y = __uint_as_float(f2tf32(bR[i].y));
            bv.z = __uint_as_float(f2tf32(bR[i].z));
            bv.w = __uint_as_float(f2tf32(bR[i].w));
            *(float4*)&Bs[brow[i] * BROWP + bcol[i]] = bv;
        }
        __syncthreads();

        if (t + 1 < nT) {
#pragma unroll
            for (int i = 0; i < 4; i++) {
                aR[i] = *(const float4*)(agp[i] + (size_t)(t + 1) * TBK);
                bR[i] = *(const float4*)(bgp[i] + (size_t)(t + 1) * TBK * N);
            }
        }

#pragma unroll
        for (int kk = 0; kk < 4; kk++) {
            float4 af[4];
#pragma unroll
            for (int im = 0; im < 4; im++) {
                int mblk = wm * 4 + im;
                af[im] = *(const float4*)&As[(mblk * 4 + kk) * ACHUNK + lane * 4];
            }
            uint32_t bf[4][2];
#pragma unroll
            for (int in = 0; in < 4; in++) {
                int n = wn * 32 + in * 8 + ln4;
                bf[in][0] = __float_as_uint(Bs[(kk * 8 + l4) * BROWP + n]);
                bf[in][1] = __float_as_uint(Bs[(kk * 8 + l4 + 4) * BROWP + n]);
            }
#pragma unroll
            for (int im = 0; im < 4; im++)
#pragma unroll
                for (int in = 0; in < 4; in++)
                    mma_tf32(acc[im][in],
                             __float_as_uint(af[im].x), __float_as_uint(af[im].y),
                             __float_as_uint(af[im].z), __float_as_uint(af[im].w),
                             bf[in][0], bf[in][1]);
        }
        __syncthreads();
    }

    const int lr = lane >> 2;
    const int lc = (lane & 3) * 2;
#pragma unroll
    for (int im = 0; im < 4; im++) {
        int r = row0 + wm * 64 + im * 16 + lr;
#pragma unroll
        for (int in = 0; in < 4; in++) {
            int c = col0 + wn * 32 + in * 8 + lc;
            float b0 = bias[c], b1 = bias[c + 1];
            float2 v0 = make_float2(acc[im][in][0] + b0, acc[im][in][1] + b1);
            float2 v1 = make_float2(acc[im][in][2] + b0, acc[im][in][3] + b1);
            *(float2*)&C[(size_t)r * N + c] = v0;
            *(float2*)&C[(size_t)(r + 8) * N + c] = v1;
        }
    }
}

// ---------------------------------------------------------------------------
// RoPE + head scatter (unchanged)
// ---------------------------------------------------------------------------
__global__ void rope_scatter_kernel(const float* __restrict__ qkv,
                                    const float2* __restrict__ rope,
                                    float* __restrict__ q, float* __restrict__ k,
                                    float* __restrict__ v) {
    int idx = blockIdx.x * blockDim.x + threadIdx.x;
    int d = idx & 63;
    int h = (idx >> 6) & 15;
    int t = (idx >> 10) & 2047;
    int b = idx >> 21;

    size_t base = (size_t)(b * TSEQ + t) * QKVCOLS + h * DHEAD;
    float2 cs = rope[t * 32 + (d & 31)];

    float qv = qkv[base + d];
    float kv = qkv[base + CDIM + d];
    float vv = qkv[base + 2 * CDIM + d];

    int dp = (d < 32) ? d + 32 : d - 32;
    float sgn = (d < 32) ? -1.0f : 1.0f;
    float qr = qkv[base + dp];
    float kr = qkv[base + CDIM + dp];

    size_t o = ((size_t)(b * NHEAD + h) * TSEQ + t) * DHEAD + d;
    q[o] = qv * cs.x + sgn * qr * cs.y;
    k[o] = kv * cs.x + sgn * kr * cs.y;
    v[o] = vv;
}

// ---------------------------------------------------------------------------
// Flash attention with tf32 mma.sync (causal).
// 64x64 tiles, 128 threads = 4 warps (warp w owns rows w*16..w*16+15).
// S = QK^T via split-tf32 (hi+lo, 3 mma) -> ~fp32 accuracy.
// PV via single tf32.
// Q pre-scaled by 0.125*log2(e); exp = single ex2.approx.
// ---------------------------------------------------------------------------
#define FQPAD 68
#define FVPAD 72
#define FS_QHI 0
#define FS_QLO 4352
#define FS_KHI 8704
#define FS_KLO 13056
#define FS_VT  17408
#define FS_P   22016
#define FLASH_SMEM_FLOATS (FS_P + 4 * 16 * FQPAD)   // 26368
#define FLASH_SMEM_BYTES (FLASH_SMEM_FLOATS * 4)    // 105472

#define NEGBIG (-1e30f)

__global__ __launch_bounds__(128)
void flash_mma_kernel(const float* __restrict__ Q, const float* __restrict__ K,
                      const float* __restrict__ V, float* __restrict__ Y) {
    extern __shared__ float fs[];
    float* Qhi = fs + FS_QHI;   // [64][68]
    float* Qlo = fs + FS_QLO;   // [64][68]
    float* Khi = fs + FS_KHI;   // [64][68]
    float* Klo = fs + FS_KLO;   // [64][68]
    float* Vt  = fs + FS_VT;    // [64][72] tf32 values

    int bh = blockIdx.y;
    int qt = gridDim.x - 1 - blockIdx.x;   // heavy tiles first
    int q0 = qt * 64;

    const float* Qb = Q + ((size_t)bh * TSEQ + q0) * DHEAD;
    const float* Kb = K + (size_t)bh * TSEQ * DHEAD;
    const float* Vb = V + (size_t)bh * TSEQ * DHEAD;

    int tid = threadIdx.x;
    int lane = tid & 31;
    int w = tid >> 5;
    int g = lane >> 2;     // 0..7
    int tig = lane & 3;    // 0..3
    float* Pw = fs + FS_P + w * (16 * FQPAD);

    const float SCL = 0.125f * 1.4426950408889634f;

    // ---- load Q tile, scale, hi/lo split ----
#pragma unroll
    for (int s = 0; s < 8; s++) {
        int f = tid + s * 128;
        int r = f >> 4;
        int c = (f & 15) << 2;
        float4 qv = ((const float4*)Qb)[f];
        qv.x *= SCL; qv.y *= SCL; qv.z *= SCL; qv.w *= SCL;
        float4 hi, lo;
        hi.x = tf32f(qv.x); lo.x = tf32f(qv.x - hi.x);
        hi.y = tf32f(qv.y); lo.y = tf32f(qv.y - hi.y);
        hi.z = tf32f(qv.z); lo.z = tf32f(qv.z - hi.z);
        hi.w = tf32f(qv.w); lo.w = tf32f(qv.w - hi.w);
        *(float4*)&Qhi[r * FQPAD + c] = hi;
        *(float4*)&Qlo[r * FQPAD + c] = lo;
    }

    // ---- prefetch K/V tile 0 into registers ----
    float4 kreg[8], vreg[8];
#pragma unroll
    for (int s = 0; s < 8; s++) {
        kreg[s] = ((const float4*)Kb)[tid + s * 128];
        vreg[s] = ((const float4*)Vb)[tid + s * 128];
    }

    float oacc[8][4];
#pragma unroll
    for (int db = 0; db < 8; db++)
#pragma unroll
        for (int r = 0; r < 4; r++) oacc[db][r] = 0.0f;
    float m0 = NEGBIG, m1 = NEGBIG, l0 = 0.0f, l1 = 0.0f;

    const int r0 = w * 16 + g;   // local Q row (and +8)

    for (int jt = 0; jt <= qt; jt++) {
        __syncthreads();   // previous iter's smem reads complete

        // ---- scatter K/V regs to smem with tf32 conversion ----
#pragma unroll
        for (int s = 0; s < 8; s++) {
            int f = tid + s * 128;
            int r = f >> 4;
            int c = (f & 15) << 2;
            float4 kv = kreg[s];
            float4 hi, lo;
            hi.x = tf32f(kv.x); lo.x = tf32f(kv.x - hi.x);
            hi.y = tf32f(kv.y); lo.y = tf32f(kv.y - hi.y);
            hi.z = tf32f(kv.z); lo.z = tf32f(kv.z - hi.z);
            hi.w = tf32f(kv.w); lo.w = tf32f(kv.w - hi.w);
            *(float4*)&Khi[r * FQPAD + c] = hi;
            *(float4*)&Klo[r * FQPAD + c] = lo;
            float4 vv = vreg[s];
            vv.x = tf32f(vv.x); vv.y = tf32f(vv.y);
            vv.z = tf32f(vv.z); vv.w = tf32f(vv.w);
            *(float4*)&Vt[r * FVPAD + c] = vv;
        }
        __syncthreads();

        // ---- prefetch next K/V tile ----
        if (jt < qt) {
            const float* Kn = Kb + (size_t)(jt + 1) * 64 * DHEAD;
            const float* Vn = Vb + (size_t)(jt + 1) * 64 * DHEAD;
#pragma unroll
            for (int s = 0; s < 8; s++) {
                kreg[s] = ((const float4*)Kn)[tid + s * 128];
                vreg[s] = ((const float4*)Vn)[tid + s * 128];
            }
        }

        // ---- S = Q K^T (split tf32: hi*hi + hi*lo + lo*hi) ----
        float sacc[8][4];
#pragma unroll
        for (int nb = 0; nb < 8; nb++)
#pragma unroll
            for (int r = 0; r < 4; r++) sacc[nb][r] = 0.0f;

#pragma unroll
        for (int ks = 0; ks < 8; ks++) {
            int kc = ks * 8 + tig;
            uint32_t ah0 = __float_as_uint(Qhi[r0 * FQPAD + kc]);
            uint32_t ah1 = __float_as_uint(Qhi[(r0 + 8) * FQPAD + kc]);
            uint32_t ah2 = __float_as_uint(Qhi[r0 * FQPAD + kc + 4]);
            uint32_t ah3 = __float_as_uint(Qhi[(r0 + 8) * FQPAD + kc + 4]);
            uint32_t al0 = __float_as_uint(Qlo[r0 * FQPAD + kc]);
            uint32_t al1 = __float_as_uint(Qlo[(r0 + 8) * FQPAD + kc]);
            uint32_t al2 = __float_as_uint(Qlo[r0 * FQPAD + kc + 4]);
            uint32_t al3 = __float_as_uint(Qlo[(r0 + 8) * FQPAD + kc + 4]);
#pragma unroll
            for (int nb = 0; nb < 8; nb++) {
                int nr = nb * 8 + g;
                uint32_t bh0 = __float_as_uint(Khi[nr * FQPAD + kc]);
                uint32_t bh1 = __float_as_uint(Khi[nr * FQPAD + kc + 4]);
                uint32_t bl0 = __float_as_uint(Klo[nr * FQPAD + kc]);
                uint32_t bl1 = __float_as_uint(Klo[nr * FQPAD + kc + 4]);
                mma_tf32(sacc[nb], ah0, ah1, ah2, ah3, bh0, bh1);
                mma_tf32(sacc[nb], ah0, ah1, ah2, ah3, bl0, bl1);
                mma_tf32(sacc[nb], al0, al1, al2, al3, bh0, bh1);
            }
        }

        // ---- causal mask (diagonal tile only) ----
        if (jt == qt) {
#pragma unroll
            for (int nb = 0; nb < 8; nb++) {
                int c0 = nb * 8 + 2 * tig;
#pragma unroll
                for (int e = 0; e < 2; e++) {
                    if (c0 + e > r0) sacc[nb][e] = NEGBIG;
                    if (c0 + e > r0 + 8) sacc[nb][2 + e] = NEGBIG;
                }
            }
        }

        // ---- online softmax (S already in log2 domain via Q pre-scale) ----
        float tm0 = NEGBIG, tm1 = NEGBIG;
#pragma unroll
        for (int nb = 0; nb < 8; nb++) {
            tm0 = fmaxf(tm0, fmaxf(sacc[nb][0], sacc[nb][1]));
            tm1 = fmaxf(tm1, fmaxf(sacc[nb][2], sacc[nb][3]));
        }
        tm0 = fmaxf(tm0, __shfl_xor_sync(0xffffffffu, tm0, 1));
        tm0 = fmaxf(tm0, __shfl_xor_sync(0xffffffffu, tm0, 2));
        tm1 = fmaxf(tm1, __shfl_xor_sync(0xffffffffu, tm1, 1));
        tm1 = fmaxf(tm1, __shfl_xor_sync(0xffffffffu, tm1, 2));

        float mn0 = fmaxf(m0, tm0);
        float mn1 = fmaxf(m1, tm1);
        float corr0 = ex2f(m0 - mn0);
        float corr1 = ex2f(m1 - mn1);
        float rs0 = 0.0f, rs1 = 0.0f;
#pragma unroll
        for (int nb = 0; nb < 8; nb++) {
            sacc[nb][0] = ex2f(sacc[nb][0] - mn0);
            sacc[nb][1] = ex2f(sacc[nb][1] - mn0);
            sacc[nb][2] = ex2f(sacc[nb][2] - mn1);
            sacc[nb][3] = ex2f(sacc[nb][3] - mn1);
            rs0 += sacc[nb][0] + sacc[nb][1];
            rs1 += sacc[nb][2] + sacc[nb][3];
        }
        rs0 += __shfl_xor_sync(0xffffffffu, rs0, 1);
        rs0 += __shfl_xor_sync(0xffffffffu, rs0, 2);
        rs1 += __shfl_xor_sync(0xffffffffu, rs1, 1);
        rs1 += __shfl_xor_sync(0xffffffffu, rs1, 2);

        l0 = l0 * corr0 + rs0;
        l1 = l1 * corr1 + rs1;
        m0 = mn0;
        m1 = mn1;
#pragma unroll
        for (int db = 0; db < 8; db++) {
            oacc[db][0] *= corr0;
            oacc[db][1] *= corr0;
            oacc[db][2] *= corr1;
            oacc[db][3] *= corr1;
        }

        // ---- store P (tf32) to per-warp smem ----
#pragma unroll
        for (int nb = 0; nb < 8; nb++) {
            int pc = nb * 8 + 2 * tig;
            float2 p01 = make_float2(tf32f(sacc[nb][0]), tf32f(sacc[nb][1]));
            float2 p23 = make_float2(tf32f(sacc[nb][2]), tf32f(sacc[nb][3]));
            *(float2*)&Pw[g * FQPAD + pc] = p01;
            *(float2*)&Pw[(g + 8) * FQPAD + pc] = p23;
        }
        __syncwarp();

        // ---- O += P @ V ----
#pragma unroll
        for (int ks = 0; ks < 8; ks++) {
            int kc = ks * 8 + tig;
            uint32_t a0 = __float_as_uint(Pw[g * FQPAD + kc]);
            uint32_t a1 = __float_as_uint(Pw[(g + 8) * FQPAD + kc]);
            uint32_t a2 = __float_as_uint(Pw[g * FQPAD + kc + 4]);
            uint32_t a3 = __float_as_uint(Pw[(g + 8) * FQPAD + kc + 4]);
#pragma unroll
            for (int db = 0; db < 8; db++) {
                uint32_t b0 = __float_as_uint(Vt[(ks * 8 + tig) * FVPAD + db * 8 + g]);
                uint32_t b1 = __float_as_uint(Vt[(ks * 8 + tig + 4) * FVPAD + db * 8 + g]);
                mma_tf32(oacc[db], a0, a1, a2, a3, b0, b1);
            }
        }
    }

    // ---- finalize: normalize and write Y[b, t, h*64 + d] ----
    float inv0 = 1.0f / l0;
    float inv1 = 1.0f / l1;
    int b = bh >> 4;
    int h = bh & 15;
    int t0 = q0 + w * 16 + g;
    int t1 = t0 + 8;
#pragma unroll
    for (int db = 0; db < 8; db++) {
        int col = h * 64 + db * 8 + 2 * tig;
        float2 y0 = make_float2(oacc[db][0] * inv0, oacc[db][1] * inv0);
        float2 y1 = make_float2(oacc[db][2] * inv1, oacc[db][3] * inv1);
        *(float2*)&g_y[(size_t)(b * TSEQ + t0) * CDIM + col] = y0;
        *(float2*)&g_y[(size_t)(b * TSEQ + t1) * CDIM + col] = y1;
    }
    (void)Y;
}

// ---------------------------------------------------------------------------
// Launch
// ---------------------------------------------------------------------------
extern "C" void kernel_launch(void* const* d_in, const int* in_sizes, int n_in,
                              void* d_out, int out_size) {
    const float* x      = (const float*)d_in[0];
    const float* w_attn = (const float*)d_in[1];
    const float* b_attn = (const float*)d_in[2];
    const float* w_proj = (const float*)d_in[3];
    const float* b_proj = (const float*)d_in[4];
    float* out = (float*)d_out;

    float *qkv, *q, *k, *v, *y;
    float2* rope;
    cudaGetSymbolAddress((void**)&qkv, g_qkv);
    cudaGetSymbolAddress((void**)&q, g_q);
    cudaGetSymbolAddress((void**)&k, g_k);
    cudaGetSymbolAddress((void**)&v, g_v);
    cudaGetSymbolAddress((void**)&y, g_y);
    cudaGetSymbolAddress((void**)&rope, g_rope);

    cudaFuncSetAttribute(gemm_tf32_kernel,
                         cudaFuncAttributeMaxDynamicSharedMemorySize,
                         GEMM_SMEM_BYTES);
    cudaFuncSetAttribute(flash_mma_kernel,
                         cudaFuncAttributeMaxDynamicSharedMemorySize,
                         FLASH_SMEM_BYTES);

    build_rope_kernel<<<(TSEQ * 32 + 255) / 256, 256>>>(rope);

    gemm_tf32_kernel<<<dim3(QKVCOLS / TBN, MROWS / TBM), 256, GEMM_SMEM_BYTES>>>(
        x, w_attn, b_attn, qkv, MROWS, QKVCOLS, CDIM);

    rope_scatter_kernel<<<(BSZ * TSEQ * CDIM) / 256, 256>>>(qkv, rope, q, k, v);

    flash_mma_kernel<<<dim3(TSEQ / 64, BSZ * NHEAD), 128, FLASH_SMEM_BYTES>>>(
        q, k, v, y);

    gemm_tf32_kernel<<<dim3(CDIM / TBN, MROWS / TBM), 256, GEMM_SMEM_BYTES>>>(
        y, w_proj, b_proj, out, MROWS, CDIM, CDIM);
}

// round 5
// speedup vs baseline: 4.4069x; 1.0918x over previous
#include <cuda_runtime.h>
#include <cuda_bf16.h>
#include <math.h>
#include <math_constants.h>
#include <stdint.h>

// Problem constants
#define BSZ 2
#define TSEQ 2048
#define CDIM 1024
#define NHEAD 16
#define DHEAD 64
#define MROWS (BSZ * TSEQ)          // 4096
#define QKVCOLS (3 * CDIM)          // 3072

// ---------------------------------------------------------------------------
// Scratch
// ---------------------------------------------------------------------------
__device__ float g_qkv[(size_t)MROWS * QKVCOLS];
__device__ __nv_bfloat16 g_qh[(size_t)BSZ * NHEAD * TSEQ * DHEAD];
__device__ __nv_bfloat16 g_ql[(size_t)BSZ * NHEAD * TSEQ * DHEAD];
__device__ __nv_bfloat16 g_kh[(size_t)BSZ * NHEAD * TSEQ * DHEAD];
__device__ __nv_bfloat16 g_kl[(size_t)BSZ * NHEAD * TSEQ * DHEAD];
__device__ float g_v[(size_t)BSZ * NHEAD * TSEQ * DHEAD];
__device__ float g_y[(size_t)MROWS * CDIM];
__device__ float2 g_rope[TSEQ * (DHEAD / 2)];

// ---------------------------------------------------------------------------
// RoPE table
// ---------------------------------------------------------------------------
__global__ void build_rope_kernel(float2* __restrict__ table) {
    int i = blockIdx.x * blockDim.x + threadIdx.x;
    if (i >= TSEQ * 32) return;
    int t = i >> 5;
    int j = i & 31;
    double inv = pow(10000.0, -(double)j / 32.0);
    double ang = (double)t * inv;
    table[i] = make_float2((float)cos(ang), (float)sin(ang));
}

// ---------------------------------------------------------------------------
// Math helpers
// ---------------------------------------------------------------------------
__device__ __forceinline__ uint32_t f2tf32(float x) {
    uint32_t r;
    asm("cvt.rna.tf32.f32 %0, %1;" : "=r"(r) : "f"(x));
    return r;
}
__device__ __forceinline__ float tf32f(float x) {
    return __uint_as_float(f2tf32(x));
}
__device__ __forceinline__ float ex2f(float x) {
    float r;
    asm("ex2.approx.ftz.f32 %0, %1;" : "=f"(r) : "f"(x));
    return r;
}
__device__ __forceinline__ void mma_tf32(float c[4], uint32_t a0, uint32_t a1,
                                         uint32_t a2, uint32_t a3,
                                         uint32_t b0, uint32_t b1) {
    asm volatile(
        "mma.sync.aligned.m16n8k8.row.col.f32.tf32.tf32.f32 "
        "{%0,%1,%2,%3}, {%4,%5,%6,%7}, {%8,%9}, {%0,%1,%2,%3};\n"
        : "+f"(c[0]), "+f"(c[1]), "+f"(c[2]), "+f"(c[3])
        : "r"(a0), "r"(a1), "r"(a2), "r"(a3), "r"(b0), "r"(b1));
}
__device__ __forceinline__ void mma_bf16(float c[4], uint32_t a0, uint32_t a1,
                                         uint32_t a2, uint32_t a3,
                                         uint32_t b0, uint32_t b1) {
    asm volatile(
        "mma.sync.aligned.m16n8k16.row.col.f32.bf16.bf16.f32 "
        "{%0,%1,%2,%3}, {%4,%5,%6,%7}, {%8,%9}, {%0,%1,%2,%3};\n"
        : "+f"(c[0]), "+f"(c[1]), "+f"(c[2]), "+f"(c[3])
        : "r"(a0), "r"(a1), "r"(a2), "r"(a3), "r"(b0), "r"(b1));
}

// ---------------------------------------------------------------------------
// TF32 tensor-core GEMM (round-2 proven version)
// ---------------------------------------------------------------------------
#define TBM 128
#define TBN 128
#define TBK 32
#define ACHUNK 132
#define ASMEM (32 * ACHUNK)
#define BROWP 132
#define BSMEM (TBK * BROWP)
#define GEMM_SMEM_BYTES ((ASMEM + BSMEM) * 4)

__global__ __launch_bounds__(256)
void gemm_tf32_kernel(const float* __restrict__ A, const float* __restrict__ B,
                      const float* __restrict__ bias, float* __restrict__ C,
                      int M, int N, int K) {
    extern __shared__ float sm[];
    float* As = sm;
    float* Bs = sm + ASMEM;

    const int tid = threadIdx.x;
    const int lane = tid & 31;
    const int warp = tid >> 5;
    const int wm = warp >> 2;
    const int wn = warp & 3;
    const int row0 = blockIdx.y * TBM;
    const int col0 = blockIdx.x * TBN;

    float acc[4][4][4];
#pragma unroll
    for (int im = 0; im < 4; im++)
#pragma unroll
        for (int in = 0; in < 4; in++)
#pragma unroll
            for (int r = 0; r < 4; r++) acc[im][in][r] = 0.0f;

    int arow[4], akb[4];
    const float* agp[4];
    int brow[4], bcol[4];
    const float* bgp[4];
#pragma unroll
    for (int i = 0; i < 4; i++) {
        int idx = tid + i * 256;
        arow[i] = idx >> 3;
        akb[i] = (idx & 7) << 2;
        agp[i] = A + (size_t)(row0 + arow[i]) * K + akb[i];
        brow[i] = idx >> 5;
        bcol[i] = (idx & 31) << 2;
        bgp[i] = B + (size_t)brow[i] * N + col0 + bcol[i];
    }

    const int nT = K / TBK;
    float4 aR[4], bR[4];
#pragma unroll
    for (int i = 0; i < 4; i++) {
        aR[i] = *(const float4*)agp[i];
        bR[i] = *(const float4*)bgp[i];
    }

    const int l4 = lane & 3;
    const int ln4 = lane >> 2;

    for (int t = 0; t < nT; t++) {
#pragma unroll
        for (int i = 0; i < 4; i++) {
            int row = arow[i];
            int chunkBase = (row >> 4) * 4;
            int laneBase = (row & 7) << 2;
            int rowbit = (row >> 3) & 1;
            float av[4] = {aR[i].x, aR[i].y, aR[i].z, aR[i].w};
#pragma unroll
            for (int j = 0; j < 4; j++) {
                int k = akb[i] + j;
                int chunk = chunkBase + (k >> 3);
                int lane_s = laneBase | (k & 3);
                int reg = (((k >> 2) & 1) << 1) | rowbit;
                As[chunk * ACHUNK + lane_s * 4 + reg] =
                    __uint_as_float(f2tf32(av[j]));
            }
            float4 bv;
            bv.x = __uint_as_float(f2tf32(bR[i].x));
            bv.y = __uint_as_float(f2tf32(bR[i].y));
            bv.z = __uint_as_float(f2tf32(bR[i].z));
            bv.w = __uint_as_float(f2tf32(bR[i].w));
            *(float4*)&Bs[brow[i] * BROWP + bcol[i]] = bv;
        }
        __syncthreads();

        if (t + 1 < nT) {
#pragma unroll
            for (int i = 0; i < 4; i++) {
                aR[i] = *(const float4*)(agp[i] + (size_t)(t + 1) * TBK);
                bR[i] = *(const float4*)(bgp[i] + (size_t)(t + 1) * TBK * N);
            }
        }

#pragma unroll
        for (int kk = 0; kk < 4; kk++) {
            float4 af[4];
#pragma unroll
            for (int im = 0; im < 4; im++) {
                int mblk = wm * 4 + im;
                af[im] = *(const float4*)&As[(mblk * 4 + kk) * ACHUNK + lane * 4];
            }
            uint32_t bf[4][2];
#pragma unroll
            for (int in = 0; in < 4; in++) {
                int n = wn * 32 + in * 8 + ln4;
                bf[in][0] = __float_as_uint(Bs[(kk * 8 + l4) * BROWP + n]);
                bf[in][1] = __float_as_uint(Bs[(kk * 8 + l4 + 4) * BROWP + n]);
            }
#pragma unroll
            for (int im = 0; im < 4; im++)
#pragma unroll
                for (int in = 0; in < 4; in++)
                    mma_tf32(acc[im][in],
                             __float_as_uint(af[im].x), __float_as_uint(af[im].y),
                             __float_as_uint(af[im].z), __float_as_uint(af[im].w),
                             bf[in][0], bf[in][1]);
        }
        __syncthreads();
    }

    const int lr = lane >> 2;
    const int lc = (lane & 3) * 2;
#pragma unroll
    for (int im = 0; im < 4; im++) {
        int r = row0 + wm * 64 + im * 16 + lr;
#pragma unroll
        for (int in = 0; in < 4; in++) {
            int c = col0 + wn * 32 + in * 8 + lc;
            float b0 = bias[c], b1 = bias[c + 1];
            float2 v0 = make_float2(acc[im][in][0] + b0, acc[im][in][1] + b1);
            float2 v1 = make_float2(acc[im][in][2] + b0, acc[im][in][3] + b1);
            *(float2*)&C[(size_t)r * N + c] = v0;
            *(float2*)&C[(size_t)(r + 8) * N + c] = v1;
        }
    }
}

// ---------------------------------------------------------------------------
// RoPE + head scatter + precision prep:
//   q -> scaled by 0.125*log2e, bf16 hi/lo split
//   k -> bf16 hi/lo split
//   v -> tf32-rounded fp32
// ---------------------------------------------------------------------------
__global__ void rope_scatter_split_kernel(const float* __restrict__ qkv,
                                          const float2* __restrict__ rope,
                                          __nv_bfloat16* __restrict__ qh,
                                          __nv_bfloat16* __restrict__ ql,
                                          __nv_bfloat16* __restrict__ kh,
                                          __nv_bfloat16* __restrict__ kl,
                                          float* __restrict__ v) {
    int idx = blockIdx.x * blockDim.x + threadIdx.x;
    int d = idx & 63;
    int h = (idx >> 6) & 15;
    int t = (idx >> 10) & 2047;
    int b = idx >> 21;

    size_t base = (size_t)(b * TSEQ + t) * QKVCOLS + h * DHEAD;
    float2 cs = rope[t * 32 + (d & 31)];

    float qv = qkv[base + d];
    float kv = qkv[base + CDIM + d];
    float vv = qkv[base + 2 * CDIM + d];

    int dp = (d < 32) ? d + 32 : d - 32;
    float sgn = (d < 32) ? -1.0f : 1.0f;
    float qr = qkv[base + dp];
    float kr = qkv[base + CDIM + dp];

    const float SCL = 0.125f * 1.4426950408889634f;
    float qrot = (qv * cs.x + sgn * qr * cs.y) * SCL;
    float krot = kv * cs.x + sgn * kr * cs.y;

    size_t o = ((size_t)(b * NHEAD + h) * TSEQ + t) * DHEAD + d;
    __nv_bfloat16 qhv = __float2bfloat16(qrot);
    __nv_bfloat16 khv = __float2bfloat16(krot);
    qh[o] = qhv;
    ql[o] = __float2bfloat16(qrot - __bfloat162float(qhv));
    kh[o] = khv;
    kl[o] = __float2bfloat16(krot - __bfloat162float(khv));
    v[o] = tf32f(vv);
}

// ---------------------------------------------------------------------------
// Flash attention, causal, 64x64 tiles, 128 threads (4 warps x 16 q-rows).
// S = QK^T via bf16 hi/lo split (3x m16n8k16).  PV via single tf32 m16n8k8.
// Q/K bf16 tiles: row stride 72 bf16 (144 B) -> conflict-free fragments.
// ---------------------------------------------------------------------------
#define BSTRIDE 144                       // bytes per bf16 tile row (72 bf16)
#define OFF_QH 0
#define OFF_QL (OFF_QH + 64 * BSTRIDE)    // 9216
#define OFF_KH (OFF_QL + 64 * BSTRIDE)    // 18432
#define OFF_KL (OFF_KH + 64 * BSTRIDE)    // 27648
#define OFF_VT (OFF_KL + 64 * BSTRIDE)    // 36864
#define FVPAD 68
#define OFF_P  (OFF_VT + 64 * FVPAD * 4)  // 54272
#define FQPAD 68
#define FLASH_SMEM_BYTES (OFF_P + 4 * 16 * FQPAD * 4)   // 71680

#define NEGBIG (-1e30f)

__global__ __launch_bounds__(128)
void flash_mma_kernel(const __nv_bfloat16* __restrict__ QH,
                      const __nv_bfloat16* __restrict__ QL,
                      const __nv_bfloat16* __restrict__ KH,
                      const __nv_bfloat16* __restrict__ KL,
                      const float* __restrict__ V) {
    extern __shared__ char smc[];
    float* Vt = (float*)(smc + OFF_VT);

    int bh = blockIdx.y;
    int qt = gridDim.x - 1 - blockIdx.x;   // heavy tiles first
    int q0 = qt * 64;

    const __nv_bfloat16* Qhb = QH + ((size_t)bh * TSEQ + q0) * DHEAD;
    const __nv_bfloat16* Qlb = QL + ((size_t)bh * TSEQ + q0) * DHEAD;
    const __nv_bfloat16* Khb = KH + (size_t)bh * TSEQ * DHEAD;
    const __nv_bfloat16* Klb = KL + (size_t)bh * TSEQ * DHEAD;
    const float* Vb = V + (size_t)bh * TSEQ * DHEAD;

    int tid = threadIdx.x;
    int lane = tid & 31;
    int w = tid >> 5;
    int g = lane >> 2;     // 0..7
    int tig = lane & 3;    // 0..3
    float* Pw = (float*)(smc + OFF_P) + w * (16 * FQPAD);

    // ---- load Q tile (bf16 hi/lo), 64x64 -> stride-72 rows ----
#pragma unroll
    for (int s = 0; s < 4; s++) {
        int f = tid + s * 128;          // 0..511 uint4s
        int r = f >> 3;
        int cb = (f & 7) * 16;          // byte col (8 bf16 per uint4)
        *(uint4*)(smc + OFF_QH + r * BSTRIDE + cb) = ((const uint4*)Qhb)[f];
        *(uint4*)(smc + OFF_QL + r * BSTRIDE + cb) = ((const uint4*)Qlb)[f];
    }

    // ---- prefetch K/V tile 0 ----
    uint4 khreg[4], klreg[4];
    float4 vreg[8];
#pragma unroll
    for (int s = 0; s < 4; s++) {
        khreg[s] = ((const uint4*)Khb)[tid + s * 128];
        klreg[s] = ((const uint4*)Klb)[tid + s * 128];
    }
#pragma unroll
    for (int s = 0; s < 8; s++)
        vreg[s] = ((const float4*)Vb)[tid + s * 128];

    float oacc[8][4];
#pragma unroll
    for (int db = 0; db < 8; db++)
#pragma unroll
        for (int r = 0; r < 4; r++) oacc[db][r] = 0.0f;
    float m0 = NEGBIG, m1 = NEGBIG, l0 = 0.0f, l1 = 0.0f;

    const int r0 = w * 16 + g;                       // owned Q rows r0, r0+8
    const int aoff = r0 * BSTRIDE + tig * 4;         // A-frag byte base
    const int boff = g * BSTRIDE + tig * 4;          // B-frag byte base

    for (int jt = 0; jt <= qt; jt++) {
        __syncthreads();
        // ---- store K (bf16) / V (fp32) tiles ----
#pragma unroll
        for (int s = 0; s < 4; s++) {
            int f = tid + s * 128;
            int r = f >> 3;
            int cb = (f & 7) * 16;
            *(uint4*)(smc + OFF_KH + r * BSTRIDE + cb) = khreg[s];
            *(uint4*)(smc + OFF_KL + r * BSTRIDE + cb) = klreg[s];
        }
#pragma unroll
        for (int s = 0; s < 8; s++) {
            int f = tid + s * 128;
            int r = f >> 4;
            int c4 = (f & 15) << 2;
            *(float4*)&Vt[r * FVPAD + c4] = vreg[s];
        }
        __syncthreads();

        // ---- prefetch next K/V tile ----
        if (jt < qt) {
            const __nv_bfloat16* Khn = Khb + (size_t)(jt + 1) * 64 * DHEAD;
            const __nv_bfloat16* Kln = Klb + (size_t)(jt + 1) * 64 * DHEAD;
            const float* Vn = Vb + (size_t)(jt + 1) * 64 * DHEAD;
#pragma unroll
            for (int s = 0; s < 4; s++) {
                khreg[s] = ((const uint4*)Khn)[tid + s * 128];
                klreg[s] = ((const uint4*)Kln)[tid + s * 128];
            }
#pragma unroll
            for (int s = 0; s < 8; s++)
                vreg[s] = ((const float4*)Vn)[tid + s * 128];
        }

        // ---- S = Q K^T (bf16 split: hi*hi + hi*lo + lo*hi) ----
        float sacc[8][4];
#pragma unroll
        for (int nb = 0; nb < 8; nb++)
#pragma unroll
            for (int r = 0; r < 4; r++) sacc[nb][r] = 0.0f;

#pragma unroll
        for (int ks = 0; ks < 4; ks++) {          // k16 steps
            const int kb = ks * 32;               // byte offset for k chunk
            uint32_t ah0 = *(const uint32_t*)(smc + OFF_QH + aoff + kb);
            uint32_t ah1 = *(const uint32_t*)(smc + OFF_QH + aoff + 8 * BSTRIDE + kb);
            uint32_t ah2 = *(const uint32_t*)(smc + OFF_QH + aoff + kb + 16);
            uint32_t ah3 = *(const uint32_t*)(smc + OFF_QH + aoff + 8 * BSTRIDE + kb + 16);
            uint32_t al0 = *(const uint32_t*)(smc + OFF_QL + aoff + kb);
            uint32_t al1 = *(const uint32_t*)(smc + OFF_QL + aoff + 8 * BSTRIDE + kb);
            uint32_t al2 = *(const uint32_t*)(smc + OFF_QL + aoff + kb + 16);
            uint32_t al3 = *(const uint32_t*)(smc + OFF_QL + aoff + 8 * BSTRIDE + kb + 16);
#pragma unroll
            for (int nb = 0; nb < 8; nb++) {
                const int bo = boff + nb * 8 * BSTRIDE + kb;
                uint32_t bh0 = *(const uint32_t*)(smc + OFF_KH + bo);
                uint32_t bh1 = *(const uint32_t*)(smc + OFF_KH + bo + 16);
                uint32_t bl0 = *(const uint32_t*)(smc + OFF_KL + bo);
                uint32_t bl1 = *(const uint32_t*)(smc + OFF_KL + bo + 16);
                mma_bf16(sacc[nb], ah0, ah1, ah2, ah3, bh0, bh1);
                mma_bf16(sacc[nb], ah0, ah1, ah2, ah3, bl0, bl1);
                mma_bf16(sacc[nb], al0, al1, al2, al3, bh0, bh1);
            }
        }

        // ---- causal mask (diagonal tile only) ----
        if (jt == qt) {
#pragma unroll
            for (int nb = 0; nb < 8; nb++) {
                int c0 = nb * 8 + 2 * tig;
#pragma unroll
                for (int e = 0; e < 2; e++) {
                    if (c0 + e > r0) sacc[nb][e] = NEGBIG;
                    if (c0 + e > r0 + 8) sacc[nb][2 + e] = NEGBIG;
                }
            }
        }

        // ---- online softmax (log2 domain; scale folded into Q) ----
        float tm0 = NEGBIG, tm1 = NEGBIG;
#pragma unroll
        for (int nb = 0; nb < 8; nb++) {
            tm0 = fmaxf(tm0, fmaxf(sacc[nb][0], sacc[nb][1]));
            tm1 = fmaxf(tm1, fmaxf(sacc[nb][2], sacc[nb][3]));
        }
        tm0 = fmaxf(tm0, __shfl_xor_sync(0xffffffffu, tm0, 1));
        tm0 = fmaxf(tm0, __shfl_xor_sync(0xffffffffu, tm0, 2));
        tm1 = fmaxf(tm1, __shfl_xor_sync(0xffffffffu, tm1, 1));
        tm1 = fmaxf(tm1, __shfl_xor_sync(0xffffffffu, tm1, 2));

        float mn0 = fmaxf(m0, tm0);
        float mn1 = fmaxf(m1, tm1);
        float corr0 = ex2f(m0 - mn0);
        float corr1 = ex2f(m1 - mn1);
        float rs0 = 0.0f, rs1 = 0.0f;
#pragma unroll
        for (int nb = 0; nb < 8; nb++) {
            sacc[nb][0] = ex2f(sacc[nb][0] - mn0);
            sacc[nb][1] = ex2f(sacc[nb][1] - mn0);
            sacc[nb][2] = ex2f(sacc[nb][2] - mn1);
            sacc[nb][3] = ex2f(sacc[nb][3] - mn1);
            rs0 += sacc[nb][0] + sacc[nb][1];
            rs1 += sacc[nb][2] + sacc[nb][3];
        }
        rs0 += __shfl_xor_sync(0xffffffffu, rs0, 1);
        rs0 += __shfl_xor_sync(0xffffffffu, rs0, 2);
        rs1 += __shfl_xor_sync(0xffffffffu, rs1, 1);
        rs1 += __shfl_xor_sync(0xffffffffu, rs1, 2);

        l0 = l0 * corr0 + rs0;
        l1 = l1 * corr1 + rs1;
        m0 = mn0;
        m1 = mn1;
#pragma unroll
        for (int db = 0; db < 8; db++) {
            oacc[db][0] *= corr0;
            oacc[db][1] *= corr0;
            oacc[db][2] *= corr1;
            oacc[db][3] *= corr1;
        }

        // ---- store P (tf32) to per-warp smem ----
#pragma unroll
        for (int nb = 0; nb < 8; nb++) {
            int pc = nb * 8 + 2 * tig;
            float2 p01 = make_float2(tf32f(sacc[nb][0]), tf32f(sacc[nb][1]));
            float2 p23 = make_float2(tf32f(sacc[nb][2]), tf32f(sacc[nb][3]));
            *(float2*)&Pw[g * FQPAD + pc] = p01;
            *(float2*)&Pw[(g + 8) * FQPAD + pc] = p23;
        }
        __syncwarp();

        // ---- O += P @ V (single tf32) ----
#pragma unroll
        for (int ks = 0; ks < 8; ks++) {
            int kc = ks * 8 + tig;
            uint32_t a0 = __float_as_uint(Pw[g * FQPAD + kc]);
            uint32_t a1 = __float_as_uint(Pw[(g + 8) * FQPAD + kc]);
            uint32_t a2 = __float_as_uint(Pw[g * FQPAD + kc + 4]);
            uint32_t a3 = __float_as_uint(Pw[(g + 8) * FQPAD + kc + 4]);
#pragma unroll
            for (int db = 0; db < 8; db++) {
                uint32_t b0 = __float_as_uint(Vt[(ks * 8 + tig) * FVPAD + db * 8 + g]);
                uint32_t b1 = __float_as_uint(Vt[(ks * 8 + tig + 4) * FVPAD + db * 8 + g]);
                mma_tf32(oacc[db], a0, a1, a2, a3, b0, b1);
            }
        }
    }

    // ---- finalize: normalize and write Y[b, t, h*64 + d] ----
    float inv0 = 1.0f / l0;
    float inv1 = 1.0f / l1;
    int b = bh >> 4;
    int h = bh & 15;
    int t0 = q0 + w * 16 + g;
    int t1 = t0 + 8;
#pragma unroll
    for (int db = 0; db < 8; db++) {
        int col = h * 64 + db * 8 + 2 * tig;
        float2 y0 = make_float2(oacc[db][0] * inv0, oacc[db][1] * inv0);
        float2 y1 = make_float2(oacc[db][2] * inv1, oacc[db][3] * inv1);
        *(float2*)&g_y[(size_t)(b * TSEQ + t0) * CDIM + col] = y0;
        *(float2*)&g_y[(size_t)(b * TSEQ + t1) * CDIM + col] = y1;
    }
}

// ---------------------------------------------------------------------------
// Launch
// ---------------------------------------------------------------------------
extern "C" void kernel_launch(void* const* d_in, const int* in_sizes, int n_in,
                              void* d_out, int out_size) {
    const float* x      = (const float*)d_in[0];
    const float* w_attn = (const float*)d_in[1];
    const float* b_attn = (const float*)d_in[2];
    const float* w_proj = (const float*)d_in[3];
    const float* b_proj = (const float*)d_in[4];
    float* out = (float*)d_out;

    float *qkv, *v, *y;
    float2* rope;
    __nv_bfloat16 *qh, *ql, *kh, *kl;
    cudaGetSymbolAddress((void**)&qkv, g_qkv);
    cudaGetSymbolAddress((void**)&qh, g_qh);
    cudaGetSymbolAddress((void**)&ql, g_ql);
    cudaGetSymbolAddress((void**)&kh, g_kh);
    cudaGetSymbolAddress((void**)&kl, g_kl);
    cudaGetSymbolAddress((void**)&v, g_v);
    cudaGetSymbolAddress((void**)&y, g_y);
    cudaGetSymbolAddress((void**)&rope, g_rope);

    cudaFuncSetAttribute(gemm_tf32_kernel,
                         cudaFuncAttributeMaxDynamicSharedMemorySize,
                         GEMM_SMEM_BYTES);
    cudaFuncSetAttribute(flash_mma_kernel,
                         cudaFuncAttributeMaxDynamicSharedMemorySize,
                         FLASH_SMEM_BYTES);

    build_rope_kernel<<<(TSEQ * 32 + 255) / 256, 256>>>(rope);

    // QKV GEMM (tf32 mma.sync)
    gemm_tf32_kernel<<<dim3(QKVCOLS / TBN, MROWS / TBM), 256, GEMM_SMEM_BYTES>>>(
        x, w_attn, b_attn, qkv, MROWS, QKVCOLS, CDIM);

    // RoPE + scatter + bf16 split + tf32 round
    rope_scatter_split_kernel<<<(BSZ * TSEQ * CDIM) / 256, 256>>>(
        qkv, rope, qh, ql, kh, kl, v);

    // Flash attention (bf16-split S, tf32 PV)
    flash_mma_kernel<<<dim3(TSEQ / 64, BSZ * NHEAD), 128, FLASH_SMEM_BYTES>>>(
        qh, ql, kh, kl, v);

    // Output projection (tf32 mma.sync)
    gemm_tf32_kernel<<<dim3(CDIM / TBN, MROWS / TBM), 256, GEMM_SMEM_BYTES>>>(
        y, w_proj, b_proj, out, MROWS, CDIM, CDIM);
}

// round 6
// speedup vs baseline: 4.4937x; 1.0197x over previous
#include <cuda_runtime.h>
#include <cuda_bf16.h>
#include <math.h>
#include <math_constants.h>
#include <stdint.h>

// Problem constants
#define BSZ 2
#define TSEQ 2048
#define CDIM 1024
#define NHEAD 16
#define DHEAD 64
#define MROWS (BSZ * TSEQ)          // 4096
#define QKVCOLS (3 * CDIM)          // 3072

// ---------------------------------------------------------------------------
// Scratch
// ---------------------------------------------------------------------------
__device__ float g_qkv[(size_t)MROWS * QKVCOLS];
__device__ __nv_bfloat16 g_qh[(size_t)BSZ * NHEAD * TSEQ * DHEAD];
__device__ __nv_bfloat16 g_ql[(size_t)BSZ * NHEAD * TSEQ * DHEAD];
__device__ __nv_bfloat16 g_kh[(size_t)BSZ * NHEAD * TSEQ * DHEAD];
__device__ __nv_bfloat16 g_kl[(size_t)BSZ * NHEAD * TSEQ * DHEAD];
__device__ __nv_bfloat16 g_vth[(size_t)BSZ * NHEAD * DHEAD * TSEQ];  // [bh][d][t]
__device__ __nv_bfloat16 g_vtl[(size_t)BSZ * NHEAD * DHEAD * TSEQ];
__device__ float g_y[(size_t)MROWS * CDIM];
__device__ float2 g_rope[TSEQ * (DHEAD / 2)];

// ---------------------------------------------------------------------------
// RoPE table
// ---------------------------------------------------------------------------
__global__ void build_rope_kernel(float2* __restrict__ table) {
    int i = blockIdx.x * blockDim.x + threadIdx.x;
    if (i >= TSEQ * 32) return;
    int t = i >> 5;
    int j = i & 31;
    double inv = pow(10000.0, -(double)j / 32.0);
    double ang = (double)t * inv;
    table[i] = make_float2((float)cos(ang), (float)sin(ang));
}

// ---------------------------------------------------------------------------
// Math helpers
// ---------------------------------------------------------------------------
__device__ __forceinline__ uint32_t f2tf32(float x) {
    uint32_t r;
    asm("cvt.rna.tf32.f32 %0, %1;" : "=r"(r) : "f"(x));
    return r;
}
__device__ __forceinline__ float ex2f(float x) {
    float r;
    asm("ex2.approx.ftz.f32 %0, %1;" : "=f"(r) : "f"(x));
    return r;
}
__device__ __forceinline__ void mma_tf32(float c[4], uint32_t a0, uint32_t a1,
                                         uint32_t a2, uint32_t a3,
                                         uint32_t b0, uint32_t b1) {
    asm volatile(
        "mma.sync.aligned.m16n8k8.row.col.f32.tf32.tf32.f32 "
        "{%0,%1,%2,%3}, {%4,%5,%6,%7}, {%8,%9}, {%0,%1,%2,%3};\n"
        : "+f"(c[0]), "+f"(c[1]), "+f"(c[2]), "+f"(c[3])
        : "r"(a0), "r"(a1), "r"(a2), "r"(a3), "r"(b0), "r"(b1));
}
__device__ __forceinline__ void mma_bf16(float c[4], uint32_t a0, uint32_t a1,
                                         uint32_t a2, uint32_t a3,
                                         uint32_t b0, uint32_t b1) {
    asm volatile(
        "mma.sync.aligned.m16n8k16.row.col.f32.bf16.bf16.f32 "
        "{%0,%1,%2,%3}, {%4,%5,%6,%7}, {%8,%9}, {%0,%1,%2,%3};\n"
        : "+f"(c[0]), "+f"(c[1]), "+f"(c[2]), "+f"(c[3])
        : "r"(a0), "r"(a1), "r"(a2), "r"(a3), "r"(b0), "r"(b1));
}
__device__ __forceinline__ void packsplit2(float p0, float p1,
                                           uint32_t& hi, uint32_t& lo) {
    __nv_bfloat162 h = __floats2bfloat162_rn(p0, p1);
    float2 f = __bfloat1622float2(h);
    __nv_bfloat162 l = __floats2bfloat162_rn(p0 - f.x, p1 - f.y);
    hi = *reinterpret_cast<uint32_t*>(&h);
    lo = *reinterpret_cast<uint32_t*>(&l);
}
__device__ __forceinline__ uint32_t smem_u32(const void* p) {
    uint32_t a;
    asm("{ .reg .u64 t; cvta.to.shared.u64 t, %1; cvt.u32.u64 %0, t; }"
        : "=r"(a) : "l"(p));
    return a;
}
__device__ __forceinline__ void cp16(uint32_t smem, const void* g) {
    asm volatile("cp.async.ca.shared.global [%0], [%1], 16;"
                 :: "r"(smem), "l"(g) : "memory");
}
#define CP_COMMIT() asm volatile("cp.async.commit_group;" ::: "memory")
#define CP_WAIT_ALL() asm volatile("cp.async.wait_group 0;" ::: "memory")

// ---------------------------------------------------------------------------
// TF32 tensor-core GEMM (round-2 proven version, unchanged)
// ---------------------------------------------------------------------------
#define TBM 128
#define TBN 128
#define TBK 32
#define ACHUNK 132
#define ASMEM (32 * ACHUNK)
#define BROWP 132
#define BSMEM (TBK * BROWP)
#define GEMM_SMEM_BYTES ((ASMEM + BSMEM) * 4)

__global__ __launch_bounds__(256)
void gemm_tf32_kernel(const float* __restrict__ A, const float* __restrict__ B,
                      const float* __restrict__ bias, float* __restrict__ C,
                      int M, int N, int K) {
    extern __shared__ float sm[];
    float* As = sm;
    float* Bs = sm + ASMEM;

    const int tid = threadIdx.x;
    const int lane = tid & 31;
    const int warp = tid >> 5;
    const int wm = warp >> 2;
    const int wn = warp & 3;
    const int row0 = blockIdx.y * TBM;
    const int col0 = blockIdx.x * TBN;

    float acc[4][4][4];
#pragma unroll
    for (int im = 0; im < 4; im++)
#pragma unroll
        for (int in = 0; in < 4; in++)
#pragma unroll
            for (int r = 0; r < 4; r++) acc[im][in][r] = 0.0f;

    int arow[4], akb[4];
    const float* agp[4];
    int brow[4], bcol[4];
    const float* bgp[4];
#pragma unroll
    for (int i = 0; i < 4; i++) {
        int idx = tid + i * 256;
        arow[i] = idx >> 3;
        akb[i] = (idx & 7) << 2;
        agp[i] = A + (size_t)(row0 + arow[i]) * K + akb[i];
        brow[i] = idx >> 5;
        bcol[i] = (idx & 31) << 2;
        bgp[i] = B + (size_t)brow[i] * N + col0 + bcol[i];
    }

    const int nT = K / TBK;
    float4 aR[4], bR[4];
#pragma unroll
    for (int i = 0; i < 4; i++) {
        aR[i] = *(const float4*)agp[i];
        bR[i] = *(const float4*)bgp[i];
    }

    const int l4 = lane & 3;
    const int ln4 = lane >> 2;

    for (int t = 0; t < nT; t++) {
#pragma unroll
        for (int i = 0; i < 4; i++) {
            int row = arow[i];
            int chunkBase = (row >> 4) * 4;
            int laneBase = (row & 7) << 2;
            int rowbit = (row >> 3) & 1;
            float av[4] = {aR[i].x, aR[i].y, aR[i].z, aR[i].w};
#pragma unroll
            for (int j = 0; j < 4; j++) {
                int k = akb[i] + j;
                int chunk = chunkBase + (k >> 3);
                int lane_s = laneBase | (k & 3);
                int reg = (((k >> 2) & 1) << 1) | rowbit;
                As[chunk * ACHUNK + lane_s * 4 + reg] =
                    __uint_as_float(f2tf32(av[j]));
            }
            float4 bv;
            bv.x = __uint_as_float(f2tf32(bR[i].x));
            bv.y = __uint_as_float(f2tf32(bR[i].y));
            bv.z = __uint_as_float(f2tf32(bR[i].z));
            bv.w = __uint_as_float(f2tf32(bR[i].w));
            *(float4*)&Bs[brow[i] * BROWP + bcol[i]] = bv;
        }
        __syncthreads();

        if (t + 1 < nT) {
#pragma unroll
            for (int i = 0; i < 4; i++) {
                aR[i] = *(const float4*)(agp[i] + (size_t)(t + 1) * TBK);
                bR[i] = *(const float4*)(bgp[i] + (size_t)(t + 1) * TBK * N);
            }
        }

#pragma unroll
        for (int kk = 0; kk < 4; kk++) {
            float4 af[4];
#pragma unroll
            for (int im = 0; im < 4; im++) {
                int mblk = wm * 4 + im;
                af[im] = *(const float4*)&As[(mblk * 4 + kk) * ACHUNK + lane * 4];
            }
            uint32_t bf[4][2];
#pragma unroll
            for (int in = 0; in < 4; in++) {
                int n = wn * 32 + in * 8 + ln4;
                bf[in][0] = __float_as_uint(Bs[(kk * 8 + l4) * BROWP + n]);
                bf[in][1] = __float_as_uint(Bs[(kk * 8 + l4 + 4) * BROWP + n]);
            }
#pragma unroll
            for (int im = 0; im < 4; im++)
#pragma unroll
                for (int in = 0; in < 4; in++)
                    mma_tf32(acc[im][in],
                             __float_as_uint(af[im].x), __float_as_uint(af[im].y),
                             __float_as_uint(af[im].z), __float_as_uint(af[im].w),
                             bf[in][0], bf[in][1]);
        }
        __syncthreads();
    }

    const int lr = lane >> 2;
    const int lc = (lane & 3) * 2;
#pragma unroll
    for (int im = 0; im < 4; im++) {
        int r = row0 + wm * 64 + im * 16 + lr;
#pragma unroll
        for (int in = 0; in < 4; in++) {
            int c = col0 + wn * 32 + in * 8 + lc;
            float b0 = bias[c], b1 = bias[c + 1];
            float2 v0 = make_float2(acc[im][in][0] + b0, acc[im][in][1] + b1);
            float2 v1 = make_float2(acc[im][in][2] + b0, acc[im][in][3] + b1);
            *(float2*)&C[(size_t)r * N + c] = v0;
            *(float2*)&C[(size_t)(r + 8) * N + c] = v1;
        }
    }
}

// ---------------------------------------------------------------------------
// RoPE + scatter + splits + V transpose.
// Block = (one 64-row t-block, one bh). 256 threads.
//   q -> scaled by 0.125*log2e, bf16 hi/lo split  [bh][t][d]
//   k -> bf16 hi/lo split                          [bh][t][d]
//   v -> bf16 hi/lo split, transposed              [bh][d][t]
// ---------------------------------------------------------------------------
__global__ __launch_bounds__(256)
void rope_scatter_split_kernel(const float* __restrict__ qkv,
                               const float2* __restrict__ rope,
                               __nv_bfloat16* __restrict__ qh,
                               __nv_bfloat16* __restrict__ ql,
                               __nv_bfloat16* __restrict__ kh,
                               __nv_bfloat16* __restrict__ kl,
                               __nv_bfloat16* __restrict__ vth,
                               __nv_bfloat16* __restrict__ vtl) {
    __shared__ __nv_bfloat16 vsh[64][66];
    __shared__ __nv_bfloat16 vsl[64][66];

    int bh = blockIdx.y;
    int tb = blockIdx.x * 64;
    int b = bh >> 4;
    int h = bh & 15;
    int tid = threadIdx.x;

    const float SCL = 0.125f * 1.4426950408889634f;

#pragma unroll
    for (int e = 0; e < 16; e++) {
        int idx = tid + e * 256;
        int tl = idx >> 6;
        int d = idx & 63;
        int t = tb + tl;
        size_t base = (size_t)(b * TSEQ + t) * QKVCOLS + h * DHEAD;
        float2 cs = rope[t * 32 + (d & 31)];

        float qv = qkv[base + d];
        float kv = qkv[base + CDIM + d];
        float vv = qkv[base + 2 * CDIM + d];
        int dp = (d < 32) ? d + 32 : d - 32;
        float sgn = (d < 32) ? -1.0f : 1.0f;
        float qr = qkv[base + dp];
        float kr = qkv[base + CDIM + dp];

        float qrot = (qv * cs.x + sgn * qr * cs.y) * SCL;
        float krot = kv * cs.x + sgn * kr * cs.y;

        size_t o = ((size_t)bh * TSEQ + t) * DHEAD + d;
        __nv_bfloat16 qhv = __float2bfloat16(qrot);
        __nv_bfloat16 khv = __float2bfloat16(krot);
        qh[o] = qhv;
        ql[o] = __float2bfloat16(qrot - __bfloat162float(qhv));
        kh[o] = khv;
        kl[o] = __float2bfloat16(krot - __bfloat162float(khv));

        __nv_bfloat16 vhv = __float2bfloat16(vv);
        vsh[d][tl] = vhv;
        vsl[d][tl] = __float2bfloat16(vv - __bfloat162float(vhv));
    }
    __syncthreads();
#pragma unroll
    for (int e = 0; e < 16; e++) {
        int idx = tid + e * 256;
        int d = idx >> 6;
        int tl = idx & 63;
        size_t o = ((size_t)bh * DHEAD + d) * TSEQ + tb + tl;
        vth[o] = vsh[d][tl];
        vtl[o] = vsl[d][tl];
    }
}

// ---------------------------------------------------------------------------
// Flash attention v3: causal, 64x64 tiles, 128 threads (4 warps).
// - Q fragments in registers for entire kernel (bf16 hi/lo)
// - K/V^T tiles via cp.async, double buffered
// - S = QK^T bf16-split (3x m16n8k16)
// - PV = bf16-split (3x m16n8k16), P taken straight from S accumulators
// ---------------------------------------------------------------------------
#define FRS 144                        // smem row stride bytes (72 bf16)
#define OFF_KH 0
#define OFF_KL 9216
#define OFF_VTH 18432
#define OFF_VTL 27648
#define BUFB 36864
#define FLASH_SMEM_BYTES (2 * BUFB)    // 73728

#define NEGBIG (-1e30f)

__global__ __launch_bounds__(128, 3)
void flash_mma_kernel(const __nv_bfloat16* __restrict__ QH,
                      const __nv_bfloat16* __restrict__ QL,
                      const __nv_bfloat16* __restrict__ KH,
                      const __nv_bfloat16* __restrict__ KL,
                      const __nv_bfloat16* __restrict__ VTH,
                      const __nv_bfloat16* __restrict__ VTL) {
    extern __shared__ char smc[];
    const uint32_t smb = smem_u32(smc);

    int bh = blockIdx.y;
    int qt = gridDim.x - 1 - blockIdx.x;   // heavy tiles first
    int q0 = qt * 64;

    int tid = threadIdx.x;
    int lane = tid & 31;
    int w = tid >> 5;
    int g = lane >> 2;     // 0..7
    int tig = lane & 3;    // 0..3
    const int r0 = w * 16 + g;

    const __nv_bfloat16* KHg = KH + (size_t)bh * TSEQ * DHEAD;
    const __nv_bfloat16* KLg = KL + (size_t)bh * TSEQ * DHEAD;
    const __nv_bfloat16* VTHg = VTH + (size_t)bh * DHEAD * TSEQ;
    const __nv_bfloat16* VTLg = VTL + (size_t)bh * DHEAD * TSEQ;

    // ---- issue tile 0 ----
    {
#pragma unroll
        for (int s = 0; s < 4; s++) {
            int f = tid + s * 128;
            int r = f >> 3;
            int c = (f & 7) * 8;                     // bf16 elements
            uint32_t ro = (uint32_t)(r * FRS + c * 2);
            cp16(smb + OFF_KH + ro, KHg + (size_t)r * DHEAD + c);
            cp16(smb + OFF_KL + ro, KLg + (size_t)r * DHEAD + c);
            cp16(smb + OFF_VTH + ro, VTHg + (size_t)r * TSEQ + c);
            cp16(smb + OFF_VTL + ro, VTLg + (size_t)r * TSEQ + c);
        }
        CP_COMMIT();
    }

    // ---- Q fragments in registers ----
    uint32_t qah[4][4], qal[4][4];
    {
        const __nv_bfloat16* Qhg = QH + ((size_t)bh * TSEQ + q0 + r0) * DHEAD;
        const __nv_bfloat16* Qlg = QL + ((size_t)bh * TSEQ + q0 + r0) * DHEAD;
#pragma unroll
        for (int ks = 0; ks < 4; ks++) {
            int c0 = ks * 16 + 2 * tig;
            qah[ks][0] = *(const uint32_t*)(Qhg + c0);
            qah[ks][1] = *(const uint32_t*)(Qhg + 8 * DHEAD + c0);
            qah[ks][2] = *(const uint32_t*)(Qhg + c0 + 8);
            qah[ks][3] = *(const uint32_t*)(Qhg + 8 * DHEAD + c0 + 8);
            qal[ks][0] = *(const uint32_t*)(Qlg + c0);
            qal[ks][1] = *(const uint32_t*)(Qlg + 8 * DHEAD + c0);
            qal[ks][2] = *(const uint32_t*)(Qlg + c0 + 8);
            qal[ks][3] = *(const uint32_t*)(Qlg + 8 * DHEAD + c0 + 8);
        }
    }

    float oacc[8][4];
#pragma unroll
    for (int db = 0; db < 8; db++)
#pragma unroll
        for (int r = 0; r < 4; r++) oacc[db][r] = 0.0f;
    float m0 = NEGBIG, m1 = NEGBIG, l0 = 0.0f, l1 = 0.0f;

    for (int jt = 0; jt <= qt; jt++) {
        CP_WAIT_ALL();
        __syncthreads();

        // issue next tile into the other buffer
        if (jt < qt) {
            int k0n = (jt + 1) * 64;
            uint32_t nb_ = smb + ((jt + 1) & 1) * BUFB;
#pragma unroll
            for (int s = 0; s < 4; s++) {
                int f = tid + s * 128;
                int r = f >> 3;
                int c = (f & 7) * 8;
                uint32_t ro = (uint32_t)(r * FRS + c * 2);
                cp16(nb_ + OFF_KH + ro, KHg + (size_t)(k0n + r) * DHEAD + c);
                cp16(nb_ + OFF_KL + ro, KLg + (size_t)(k0n + r) * DHEAD + c);
                cp16(nb_ + OFF_VTH + ro, VTHg + (size_t)r * TSEQ + k0n + c);
                cp16(nb_ + OFF_VTL + ro, VTLg + (size_t)r * TSEQ + k0n + c);
            }
            CP_COMMIT();
        }

        const char* buf = smc + (jt & 1) * BUFB;

        // ---- S = Q K^T (bf16 split) ----
        float sacc[8][4];
#pragma unroll
        for (int nb = 0; nb < 8; nb++)
#pragma unroll
            for (int r = 0; r < 4; r++) sacc[nb][r] = 0.0f;

#pragma unroll
        for (int ks = 0; ks < 4; ks++) {
            const int kb = ks * 32;
#pragma unroll
            for (int nb = 0; nb < 8; nb++) {
                const int bo = (nb * 8 + g) * FRS + tig * 4 + kb;
                uint32_t bh0 = *(const uint32_t*)(buf + OFF_KH + bo);
                uint32_t bh1 = *(const uint32_t*)(buf + OFF_KH + bo + 16);
                uint32_t bl0 = *(const uint32_t*)(buf + OFF_KL + bo);
                uint32_t bl1 = *(const uint32_t*)(buf + OFF_KL + bo + 16);
                mma_bf16(sacc[nb], qah[ks][0], qah[ks][1], qah[ks][2], qah[ks][3], bh0, bh1);
                mma_bf16(sacc[nb], qah[ks][0], qah[ks][1], qah[ks][2], qah[ks][3], bl0, bl1);
                mma_bf16(sacc[nb], qal[ks][0], qal[ks][1], qal[ks][2], qal[ks][3], bh0, bh1);
            }
        }

        // ---- causal mask (diagonal tile only) ----
        if (jt == qt) {
#pragma unroll
            for (int nb = 0; nb < 8; nb++) {
                int c0 = nb * 8 + 2 * tig;
#pragma unroll
                for (int e = 0; e < 2; e++) {
                    if (c0 + e > r0) sacc[nb][e] = NEGBIG;
                    if (c0 + e > r0 + 8) sacc[nb][2 + e] = NEGBIG;
                }
            }
        }

        // ---- online softmax (log2 domain) ----
        float tm0 = NEGBIG, tm1 = NEGBIG;
#pragma unroll
        for (int nb = 0; nb < 8; nb++) {
            tm0 = fmaxf(tm0, fmaxf(sacc[nb][0], sacc[nb][1]));
            tm1 = fmaxf(tm1, fmaxf(sacc[nb][2], sacc[nb][3]));
        }
        tm0 = fmaxf(tm0, __shfl_xor_sync(0xffffffffu, tm0, 1));
        tm0 = fmaxf(tm0, __shfl_xor_sync(0xffffffffu, tm0, 2));
        tm1 = fmaxf(tm1, __shfl_xor_sync(0xffffffffu, tm1, 1));
        tm1 = fmaxf(tm1, __shfl_xor_sync(0xffffffffu, tm1, 2));

        float mn0 = fmaxf(m0, tm0);
        float mn1 = fmaxf(m1, tm1);
        float corr0 = ex2f(m0 - mn0);
        float corr1 = ex2f(m1 - mn1);
        float rs0 = 0.0f, rs1 = 0.0f;
#pragma unroll
        for (int nb = 0; nb < 8; nb++) {
            sacc[nb][0] = ex2f(sacc[nb][0] - mn0);
            sacc[nb][1] = ex2f(sacc[nb][1] - mn0);
            sacc[nb][2] = ex2f(sacc[nb][2] - mn1);
            sacc[nb][3] = ex2f(sacc[nb][3] - mn1);
            rs0 += sacc[nb][0] + sacc[nb][1];
            rs1 += sacc[nb][2] + sacc[nb][3];
        }
        rs0 += __shfl_xor_sync(0xffffffffu, rs0, 1);
        rs0 += __shfl_xor_sync(0xffffffffu, rs0, 2);
        rs1 += __shfl_xor_sync(0xffffffffu, rs1, 1);
        rs1 += __shfl_xor_sync(0xffffffffu, rs1, 2);

        l0 = l0 * corr0 + rs0;
        l1 = l1 * corr1 + rs1;
        m0 = mn0;
        m1 = mn1;
#pragma unroll
        for (int db = 0; db < 8; db++) {
            oacc[db][0] *= corr0;
            oacc[db][1] *= corr0;
            oacc[db][2] *= corr1;
            oacc[db][3] *= corr1;
        }

        // ---- O += P @ V  (bf16 split, P from registers) ----
#pragma unroll
        for (int ks = 0; ks < 4; ks++) {
            uint32_t ph[4], pl[4];
            packsplit2(sacc[2 * ks][0], sacc[2 * ks][1], ph[0], pl[0]);
            packsplit2(sacc[2 * ks][2], sacc[2 * ks][3], ph[1], pl[1]);
            packsplit2(sacc[2 * ks + 1][0], sacc[2 * ks + 1][1], ph[2], pl[2]);
            packsplit2(sacc[2 * ks + 1][2], sacc[2 * ks + 1][3], ph[3], pl[3]);
            const int kb = ks * 32;
#pragma unroll
            for (int db = 0; db < 8; db++) {
                const int vo = (db * 8 + g) * FRS + tig * 4 + kb;
                uint32_t vh0 = *(const uint32_t*)(buf + OFF_VTH + vo);
                uint32_t vh1 = *(const uint32_t*)(buf + OFF_VTH + vo + 16);
                uint32_t vl0 = *(const uint32_t*)(buf + OFF_VTL + vo);
                uint32_t vl1 = *(const uint32_t*)(buf + OFF_VTL + vo + 16);
                mma_bf16(oacc[db], ph[0], ph[1], ph[2], ph[3], vh0, vh1);
                mma_bf16(oacc[db], ph[0], ph[1], ph[2], ph[3], vl0, vl1);
                mma_bf16(oacc[db], pl[0], pl[1], pl[2], pl[3], vh0, vh1);
            }
        }
    }

    // ---- finalize: normalize and write Y[b, t, h*64 + d] ----
    float inv0 = 1.0f / l0;
    float inv1 = 1.0f / l1;
    int b = bh >> 4;
    int h = bh & 15;
    int t0 = q0 + r0;
    int t1 = t0 + 8;
#pragma unroll
    for (int db = 0; db < 8; db++) {
        int col = h * 64 + db * 8 + 2 * tig;
        float2 y0 = make_float2(oacc[db][0] * inv0, oacc[db][1] * inv0);
        float2 y1 = make_float2(oacc[db][2] * inv1, oacc[db][3] * inv1);
        *(float2*)&g_y[(size_t)(b * TSEQ + t0) * CDIM + col] = y0;
        *(float2*)&g_y[(size_t)(b * TSEQ + t1) * CDIM + col] = y1;
    }
}

// ---------------------------------------------------------------------------
// Launch
// ---------------------------------------------------------------------------
extern "C" void kernel_launch(void* const* d_in, const int* in_sizes, int n_in,
                              void* d_out, int out_size) {
    const float* x      = (const float*)d_in[0];
    const float* w_attn = (const float*)d_in[1];
    const float* b_attn = (const float*)d_in[2];
    const float* w_proj = (const float*)d_in[3];
    const float* b_proj = (const float*)d_in[4];
    float* out = (float*)d_out;

    float *qkv, *y;
    float2* rope;
    __nv_bfloat16 *qh, *ql, *kh, *kl, *vth, *vtl;
    cudaGetSymbolAddress((void**)&qkv, g_qkv);
    cudaGetSymbolAddress((void**)&qh, g_qh);
    cudaGetSymbolAddress((void**)&ql, g_ql);
    cudaGetSymbolAddress((void**)&kh, g_kh);
    cudaGetSymbolAddress((void**)&kl, g_kl);
    cudaGetSymbolAddress((void**)&vth, g_vth);
    cudaGetSymbolAddress((void**)&vtl, g_vtl);
    cudaGetSymbolAddress((void**)&y, g_y);
    cudaGetSymbolAddress((void**)&rope, g_rope);

    cudaFuncSetAttribute(gemm_tf32_kernel,
                         cudaFuncAttributeMaxDynamicSharedMemorySize,
                         GEMM_SMEM_BYTES);
    cudaFuncSetAttribute(flash_mma_kernel,
                         cudaFuncAttributeMaxDynamicSharedMemorySize,
                         FLASH_SMEM_BYTES);

    build_rope_kernel<<<(TSEQ * 32 + 255) / 256, 256>>>(rope);

    // QKV GEMM (tf32 mma.sync)
    gemm_tf32_kernel<<<dim3(QKVCOLS / TBN, MROWS / TBM), 256, GEMM_SMEM_BYTES>>>(
        x, w_attn, b_attn, qkv, MROWS, QKVCOLS, CDIM);

    // RoPE + scatter + splits + V transpose
    rope_scatter_split_kernel<<<dim3(TSEQ / 64, BSZ * NHEAD), 256>>>(
        qkv, rope, qh, ql, kh, kl, vth, vtl);

    // Flash attention v3
    flash_mma_kernel<<<dim3(TSEQ / 64, BSZ * NHEAD), 128, FLASH_SMEM_BYTES>>>(
        qh, ql, kh, kl, vth, vtl);

    // Output projection (tf32 mma.sync)
    gemm_tf32_kernel<<<dim3(CDIM / TBN, MROWS / TBM), 256, GEMM_SMEM_BYTES>>>(
        y, w_proj, b_proj, out, MROWS, CDIM, CDIM);
}

// round 7
// speedup vs baseline: 4.7971x; 1.0675x over previous
#include <cuda_runtime.h>
#include <cuda_bf16.h>
#include <math.h>
#include <math_constants.h>
#include <stdint.h>

// Problem constants
#define BSZ 2
#define TSEQ 2048
#define CDIM 1024
#define NHEAD 16
#define DHEAD 64
#define MROWS (BSZ * TSEQ)          // 4096
#define QKVCOLS (3 * CDIM)          // 3072

// ---------------------------------------------------------------------------
// Scratch
// ---------------------------------------------------------------------------
__device__ float g_qkv[(size_t)MROWS * QKVCOLS];
__device__ float g_xt[(size_t)MROWS * CDIM];          // tf32-rounded x
__device__ float g_wat[(size_t)CDIM * QKVCOLS];       // tf32-rounded w_attn
__device__ float g_wpt[(size_t)CDIM * CDIM];          // tf32-rounded w_proj
__device__ __nv_bfloat16 g_qh[(size_t)BSZ * NHEAD * TSEQ * DHEAD];
__device__ __nv_bfloat16 g_ql[(size_t)BSZ * NHEAD * TSEQ * DHEAD];
__device__ __nv_bfloat16 g_kh[(size_t)BSZ * NHEAD * TSEQ * DHEAD];
__device__ __nv_bfloat16 g_kl[(size_t)BSZ * NHEAD * TSEQ * DHEAD];
__device__ __nv_bfloat16 g_vth[(size_t)BSZ * NHEAD * DHEAD * TSEQ];  // [bh][d][t]
__device__ __nv_bfloat16 g_vtl[(size_t)BSZ * NHEAD * DHEAD * TSEQ];
__device__ float g_y[(size_t)MROWS * CDIM];           // tf32-rounded attn out
__device__ float2 g_rope[TSEQ * (DHEAD / 2)];

// ---------------------------------------------------------------------------
// RoPE table
// ---------------------------------------------------------------------------
__global__ void build_rope_kernel(float2* __restrict__ table) {
    int i = blockIdx.x * blockDim.x + threadIdx.x;
    if (i >= TSEQ * 32) return;
    int t = i >> 5;
    int j = i & 31;
    double inv = pow(10000.0, -(double)j / 32.0);
    double ang = (double)t * inv;
    table[i] = make_float2((float)cos(ang), (float)sin(ang));
}

// ---------------------------------------------------------------------------
// Math helpers
// ---------------------------------------------------------------------------
__device__ __forceinline__ uint32_t f2tf32(float x) {
    uint32_t r;
    asm("cvt.rna.tf32.f32 %0, %1;" : "=r"(r) : "f"(x));
    return r;
}
__device__ __forceinline__ float tf32f(float x) {
    return __uint_as_float(f2tf32(x));
}
__device__ __forceinline__ float ex2f(float x) {
    float r;
    asm("ex2.approx.ftz.f32 %0, %1;" : "=f"(r) : "f"(x));
    return r;
}
__device__ __forceinline__ void mma_tf32(float c[4], uint32_t a0, uint32_t a1,
                                         uint32_t a2, uint32_t a3,
                                         uint32_t b0, uint32_t b1) {
    asm volatile(
        "mma.sync.aligned.m16n8k8.row.col.f32.tf32.tf32.f32 "
        "{%0,%1,%2,%3}, {%4,%5,%6,%7}, {%8,%9}, {%0,%1,%2,%3};\n"
        : "+f"(c[0]), "+f"(c[1]), "+f"(c[2]), "+f"(c[3])
        : "r"(a0), "r"(a1), "r"(a2), "r"(a3), "r"(b0), "r"(b1));
}
__device__ __forceinline__ void mma_bf16(float c[4], uint32_t a0, uint32_t a1,
                                         uint32_t a2, uint32_t a3,
                                         uint32_t b0, uint32_t b1) {
    asm volatile(
        "mma.sync.aligned.m16n8k16.row.col.f32.bf16.bf16.f32 "
        "{%0,%1,%2,%3}, {%4,%5,%6,%7}, {%8,%9}, {%0,%1,%2,%3};\n"
        : "+f"(c[0]), "+f"(c[1]), "+f"(c[2]), "+f"(c[3])
        : "r"(a0), "r"(a1), "r"(a2), "r"(a3), "r"(b0), "r"(b1));
}
__device__ __forceinline__ void packsplit2(float p0, float p1,
                                           uint32_t& hi, uint32_t& lo) {
    __nv_bfloat162 h = __floats2bfloat162_rn(p0, p1);
    float2 f = __bfloat1622float2(h);
    __nv_bfloat162 l = __floats2bfloat162_rn(p0 - f.x, p1 - f.y);
    hi = *reinterpret_cast<uint32_t*>(&h);
    lo = *reinterpret_cast<uint32_t*>(&l);
}
__device__ __forceinline__ uint32_t smem_u32(const void* p) {
    uint32_t a;
    asm("{ .reg .u64 t; cvta.to.shared.u64 t, %1; cvt.u32.u64 %0, t; }"
        : "=r"(a) : "l"(p));
    return a;
}
__device__ __forceinline__ void cp16(uint32_t smem, const void* g) {
    asm volatile("cp.async.ca.shared.global [%0], [%1], 16;"
                 :: "r"(smem), "l"(g) : "memory");
}
#define CP_COMMIT() asm volatile("cp.async.commit_group;" ::: "memory")
#define CP_WAIT0() asm volatile("cp.async.wait_group 0;" ::: "memory")
#define CP_WAIT1() asm volatile("cp.async.wait_group 1;" ::: "memory")

// ---------------------------------------------------------------------------
// tf32 pre-round: out[i] = tf32(in[i])
// ---------------------------------------------------------------------------
__global__ void cvt_tf32_kernel(const float* __restrict__ in,
                                float* __restrict__ out, int n4) {
    int i = blockIdx.x * blockDim.x + threadIdx.x;
    if (i >= n4) return;
    float4 v = ((const float4*)in)[i];
    v.x = tf32f(v.x); v.y = tf32f(v.y);
    v.z = tf32f(v.z); v.w = tf32f(v.w);
    ((float4*)out)[i] = v;
}

// ---------------------------------------------------------------------------
// TF32 GEMM v2: pre-converted operands, cp.async 2-stage pipeline.
// C[M,N] = A[M,K] @ B[K,N] + bias.  128x128x32 tile, 256 thr, 8 warps (2x4).
// A smem [128][36] fp32, B smem [32][136] fp32 (bank-conflict-free frags).
// ---------------------------------------------------------------------------
#define V2_AS 36
#define V2_BS 136
#define V2_ABUF (128 * V2_AS)          // 4608 floats
#define V2_BBUF (32 * V2_BS)           // 4352 floats
#define V2_SMEM_FLOATS (2 * (V2_ABUF + V2_BBUF))
#define GEMM_SMEM_BYTES (V2_SMEM_FLOATS * 4)   // 71680

__global__ __launch_bounds__(256, 2)
void gemm_tf32_kernel(const float* __restrict__ A, const float* __restrict__ B,
                      const float* __restrict__ bias, float* __restrict__ C,
                      int M, int N, int K) {
    extern __shared__ float sm[];
    // layout: A0 | A1 | B0 | B1
    const uint32_t smb = smem_u32(sm);
    const uint32_t aoffs[2] = {0u, (uint32_t)(V2_ABUF * 4)};
    const uint32_t boffs[2] = {(uint32_t)(2 * V2_ABUF * 4),
                               (uint32_t)((2 * V2_ABUF + V2_BBUF) * 4)};

    const int tid = threadIdx.x;
    const int lane = tid & 31;
    const int warp = tid >> 5;
    const int wm = warp >> 2;      // 0..1
    const int wn = warp & 3;       // 0..3
    const int g = lane >> 2;       // 0..7
    const int tig = lane & 3;      // 0..3
    const int row0 = blockIdx.y * 128;
    const int col0 = blockIdx.x * 128;

    float acc[4][4][4];
#pragma unroll
    for (int im = 0; im < 4; im++)
#pragma unroll
        for (int in = 0; in < 4; in++)
#pragma unroll
            for (int r = 0; r < 4; r++) acc[im][in][r] = 0.0f;

    // loader maps
    int ar[4], ac4[4], br_[4], bn4[4];
#pragma unroll
    for (int s = 0; s < 4; s++) {
        int f = tid + s * 256;
        ar[s] = f >> 3;            // 0..127
        ac4[s] = (f & 7) * 4;      // 0..28
        br_[s] = f >> 5;           // 0..31
        bn4[s] = (f & 31) * 4;     // 0..124
    }

    const int nT = K / 32;

    // prologue: stage 0
#pragma unroll
    for (int s = 0; s < 4; s++) {
        cp16(smb + aoffs[0] + (uint32_t)(ar[s] * V2_AS + ac4[s]) * 4,
             A + (size_t)(row0 + ar[s]) * K + ac4[s]);
        cp16(smb + boffs[0] + (uint32_t)(br_[s] * V2_BS + bn4[s]) * 4,
             B + (size_t)br_[s] * N + col0 + bn4[s]);
    }
    CP_COMMIT();

    for (int t = 0; t < nT; t++) {
        if (t + 1 < nT) {
            const int kc = (t + 1) * 32;
            const int bsel = (t + 1) & 1;
#pragma unroll
            for (int s = 0; s < 4; s++) {
                cp16(smb + aoffs[bsel] + (uint32_t)(ar[s] * V2_AS + ac4[s]) * 4,
                     A + (size_t)(row0 + ar[s]) * K + kc + ac4[s]);
                cp16(smb + boffs[bsel] + (uint32_t)(br_[s] * V2_BS + bn4[s]) * 4,
                     B + (size_t)(kc + br_[s]) * N + col0 + bn4[s]);
            }
            CP_COMMIT();
            CP_WAIT1();
        } else {
            CP_WAIT0();
        }
        __syncthreads();

        const float* As = sm + (t & 1) * V2_ABUF;
        const float* Bs = sm + 2 * V2_ABUF + (t & 1) * V2_BBUF;

#pragma unroll
        for (int kk = 0; kk < 4; kk++) {
            uint32_t af[4][4];
#pragma unroll
            for (int im = 0; im < 4; im++) {
                int mr = wm * 64 + im * 16 + g;
                int kc = kk * 8 + tig;
                af[im][0] = __float_as_uint(As[mr * V2_AS + kc]);
                af[im][1] = __float_as_uint(As[(mr + 8) * V2_AS + kc]);
                af[im][2] = __float_as_uint(As[mr * V2_AS + kc + 4]);
                af[im][3] = __float_as_uint(As[(mr + 8) * V2_AS + kc + 4]);
            }
            uint32_t bf[4][2];
#pragma unroll
            for (int in = 0; in < 4; in++) {
                int n = wn * 32 + in * 8 + g;
                bf[in][0] = __float_as_uint(Bs[(kk * 8 + tig) * V2_BS + n]);
                bf[in][1] = __float_as_uint(Bs[(kk * 8 + tig + 4) * V2_BS + n]);
            }
#pragma unroll
            for (int im = 0; im < 4; im++)
#pragma unroll
                for (int in = 0; in < 4; in++)
                    mma_tf32(acc[im][in], af[im][0], af[im][1], af[im][2],
                             af[im][3], bf[in][0], bf[in][1]);
        }
        __syncthreads();
    }

    // epilogue (acc layout: rows g + {0,8}, cols 2*tig + {0,1})
    const int lr = g;
    const int lc = tig * 2;
#pragma unroll
    for (int im = 0; im < 4; im++) {
        int r = row0 + wm * 64 + im * 16 + lr;
#pragma unroll
        for (int in = 0; in < 4; in++) {
            int c = col0 + wn * 32 + in * 8 + lc;
            float b0 = bias[c], b1 = bias[c + 1];
            float2 v0 = make_float2(acc[im][in][0] + b0, acc[im][in][1] + b1);
            float2 v1 = make_float2(acc[im][in][2] + b0, acc[im][in][3] + b1);
            *(float2*)&C[(size_t)r * N + c] = v0;
            *(float2*)&C[(size_t)(r + 8) * N + c] = v1;
        }
    }
}

// ---------------------------------------------------------------------------
// RoPE + scatter + splits + V transpose (unchanged from round 6)
// ---------------------------------------------------------------------------
__global__ __launch_bounds__(256)
void rope_scatter_split_kernel(const float* __restrict__ qkv,
                               const float2* __restrict__ rope,
                               __nv_bfloat16* __restrict__ qh,
                               __nv_bfloat16* __restrict__ ql,
                               __nv_bfloat16* __restrict__ kh,
                               __nv_bfloat16* __restrict__ kl,
                               __nv_bfloat16* __restrict__ vth,
                               __nv_bfloat16* __restrict__ vtl) {
    __shared__ __nv_bfloat16 vsh[64][66];
    __shared__ __nv_bfloat16 vsl[64][66];

    int bh = blockIdx.y;
    int tb = blockIdx.x * 64;
    int b = bh >> 4;
    int h = bh & 15;
    int tid = threadIdx.x;

    const float SCL = 0.125f * 1.4426950408889634f;

#pragma unroll
    for (int e = 0; e < 16; e++) {
        int idx = tid + e * 256;
        int tl = idx >> 6;
        int d = idx & 63;
        int t = tb + tl;
        size_t base = (size_t)(b * TSEQ + t) * QKVCOLS + h * DHEAD;
        float2 cs = rope[t * 32 + (d & 31)];

        float qv = qkv[base + d];
        float kv = qkv[base + CDIM + d];
        float vv = qkv[base + 2 * CDIM + d];
        int dp = (d < 32) ? d + 32 : d - 32;
        float sgn = (d < 32) ? -1.0f : 1.0f;
        float qr = qkv[base + dp];
        float kr = qkv[base + CDIM + dp];

        float qrot = (qv * cs.x + sgn * qr * cs.y) * SCL;
        float krot = kv * cs.x + sgn * kr * cs.y;

        size_t o = ((size_t)bh * TSEQ + t) * DHEAD + d;
        __nv_bfloat16 qhv = __float2bfloat16(qrot);
        __nv_bfloat16 khv = __float2bfloat16(krot);
        qh[o] = qhv;
        ql[o] = __float2bfloat16(qrot - __bfloat162float(qhv));
        kh[o] = khv;
        kl[o] = __float2bfloat16(krot - __bfloat162float(khv));

        __nv_bfloat16 vhv = __float2bfloat16(vv);
        vsh[d][tl] = vhv;
        vsl[d][tl] = __float2bfloat16(vv - __bfloat162float(vhv));
    }
    __syncthreads();
#pragma unroll
    for (int e = 0; e < 16; e++) {
        int idx = tid + e * 256;
        int d = idx >> 6;
        int tl = idx & 63;
        size_t o = ((size_t)bh * DHEAD + d) * TSEQ + tb + tl;
        vth[o] = vsh[d][tl];
        vtl[o] = vsl[d][tl];
    }
}

// ---------------------------------------------------------------------------
// Flash attention v3 (round 6), epilogue now writes tf32-rounded y.
// ---------------------------------------------------------------------------
#define FRS 144
#define OFF_KH 0
#define OFF_KL 9216
#define OFF_VTH 18432
#define OFF_VTL 27648
#define BUFB 36864
#define FLASH_SMEM_BYTES (2 * BUFB)

#define NEGBIG (-1e30f)

__global__ __launch_bounds__(128, 3)
void flash_mma_kernel(const __nv_bfloat16* __restrict__ QH,
                      const __nv_bfloat16* __restrict__ QL,
                      const __nv_bfloat16* __restrict__ KH,
                      const __nv_bfloat16* __restrict__ KL,
                      const __nv_bfloat16* __restrict__ VTH,
                      const __nv_bfloat16* __restrict__ VTL) {
    extern __shared__ char smc[];
    const uint32_t smb = smem_u32(smc);

    int bh = blockIdx.y;
    int qt = gridDim.x - 1 - blockIdx.x;
    int q0 = qt * 64;

    int tid = threadIdx.x;
    int lane = tid & 31;
    int w = tid >> 5;
    int g = lane >> 2;
    int tig = lane & 3;
    const int r0 = w * 16 + g;

    const __nv_bfloat16* KHg = KH + (size_t)bh * TSEQ * DHEAD;
    const __nv_bfloat16* KLg = KL + (size_t)bh * TSEQ * DHEAD;
    const __nv_bfloat16* VTHg = VTH + (size_t)bh * DHEAD * TSEQ;
    const __nv_bfloat16* VTLg = VTL + (size_t)bh * DHEAD * TSEQ;

    {
#pragma unroll
        for (int s = 0; s < 4; s++) {
            int f = tid + s * 128;
            int r = f >> 3;
            int c = (f & 7) * 8;
            uint32_t ro = (uint32_t)(r * FRS + c * 2);
            cp16(smb + OFF_KH + ro, KHg + (size_t)r * DHEAD + c);
            cp16(smb + OFF_KL + ro, KLg + (size_t)r * DHEAD + c);
            cp16(smb + OFF_VTH + ro, VTHg + (size_t)r * TSEQ + c);
            cp16(smb + OFF_VTL + ro, VTLg + (size_t)r * TSEQ + c);
        }
        CP_COMMIT();
    }

    uint32_t qah[4][4], qal[4][4];
    {
        const __nv_bfloat16* Qhg = QH + ((size_t)bh * TSEQ + q0 + r0) * DHEAD;
        const __nv_bfloat16* Qlg = QL + ((size_t)bh * TSEQ + q0 + r0) * DHEAD;
#pragma unroll
        for (int ks = 0; ks < 4; ks++) {
            int c0 = ks * 16 + 2 * tig;
            qah[ks][0] = *(const uint32_t*)(Qhg + c0);
            qah[ks][1] = *(const uint32_t*)(Qhg + 8 * DHEAD + c0);
            qah[ks][2] = *(const uint32_t*)(Qhg + c0 + 8);
            qah[ks][3] = *(const uint32_t*)(Qhg + 8 * DHEAD + c0 + 8);
            qal[ks][0] = *(const uint32_t*)(Qlg + c0);
            qal[ks][1] = *(const uint32_t*)(Qlg + 8 * DHEAD + c0);
            qal[ks][2] = *(const uint32_t*)(Qlg + c0 + 8);
            qal[ks][3] = *(const uint32_t*)(Qlg + 8 * DHEAD + c0 + 8);
        }
    }

    float oacc[8][4];
#pragma unroll
    for (int db = 0; db < 8; db++)
#pragma unroll
        for (int r = 0; r < 4; r++) oacc[db][r] = 0.0f;
    float m0 = NEGBIG, m1 = NEGBIG, l0 = 0.0f, l1 = 0.0f;

    for (int jt = 0; jt <= qt; jt++) {
        CP_WAIT0();
        __syncthreads();

        if (jt < qt) {
            int k0n = (jt + 1) * 64;
            uint32_t nb_ = smb + ((jt + 1) & 1) * BUFB;
#pragma unroll
            for (int s = 0; s < 4; s++) {
                int f = tid + s * 128;
                int r = f >> 3;
                int c = (f & 7) * 8;
                uint32_t ro = (uint32_t)(r * FRS + c * 2);
                cp16(nb_ + OFF_KH + ro, KHg + (size_t)(k0n + r) * DHEAD + c);
                cp16(nb_ + OFF_KL + ro, KLg + (size_t)(k0n + r) * DHEAD + c);
                cp16(nb_ + OFF_VTH + ro, VTHg + (size_t)r * TSEQ + k0n + c);
                cp16(nb_ + OFF_VTL + ro, VTLg + (size_t)r * TSEQ + k0n + c);
            }
            CP_COMMIT();
        }

        const char* buf = smc + (jt & 1) * BUFB;

        float sacc[8][4];
#pragma unroll
        for (int nb = 0; nb < 8; nb++)
#pragma unroll
            for (int r = 0; r < 4; r++) sacc[nb][r] = 0.0f;

#pragma unroll
        for (int ks = 0; ks < 4; ks++) {
            const int kb = ks * 32;
#pragma unroll
            for (int nb = 0; nb < 8; nb++) {
                const int bo = (nb * 8 + g) * FRS + tig * 4 + kb;
                uint32_t bh0 = *(const uint32_t*)(buf + OFF_KH + bo);
                uint32_t bh1 = *(const uint32_t*)(buf + OFF_KH + bo + 16);
                uint32_t bl0 = *(const uint32_t*)(buf + OFF_KL + bo);
                uint32_t bl1 = *(const uint32_t*)(buf + OFF_KL + bo + 16);
                mma_bf16(sacc[nb], qah[ks][0], qah[ks][1], qah[ks][2], qah[ks][3], bh0, bh1);
                mma_bf16(sacc[nb], qah[ks][0], qah[ks][1], qah[ks][2], qah[ks][3], bl0, bl1);
                mma_bf16(sacc[nb], qal[ks][0], qal[ks][1], qal[ks][2], qal[ks][3], bh0, bh1);
            }
        }

        if (jt == qt) {
#pragma unroll
            for (int nb = 0; nb < 8; nb++) {
                int c0 = nb * 8 + 2 * tig;
#pragma unroll
                for (int e = 0; e < 2; e++) {
                    if (c0 + e > r0) sacc[nb][e] = NEGBIG;
                    if (c0 + e > r0 + 8) sacc[nb][2 + e] = NEGBIG;
                }
            }
        }

        float tm0 = NEGBIG, tm1 = NEGBIG;
#pragma unroll
        for (int nb = 0; nb < 8; nb++) {
            tm0 = fmaxf(tm0, fmaxf(sacc[nb][0], sacc[nb][1]));
            tm1 = fmaxf(tm1, fmaxf(sacc[nb][2], sacc[nb][3]));
        }
        tm0 = fmaxf(tm0, __shfl_xor_sync(0xffffffffu, tm0, 1));
        tm0 = fmaxf(tm0, __shfl_xor_sync(0xffffffffu, tm0, 2));
        tm1 = fmaxf(tm1, __shfl_xor_sync(0xffffffffu, tm1, 1));
        tm1 = fmaxf(tm1, __shfl_xor_sync(0xffffffffu, tm1, 2));

        float mn0 = fmaxf(m0, tm0);
        float mn1 = fmaxf(m1, tm1);
        float corr0 = ex2f(m0 - mn0);
        float corr1 = ex2f(m1 - mn1);
        float rs0 = 0.0f, rs1 = 0.0f;
#pragma unroll
        for (int nb = 0; nb < 8; nb++) {
            sacc[nb][0] = ex2f(sacc[nb][0] - mn0);
            sacc[nb][1] = ex2f(sacc[nb][1] - mn0);
            sacc[nb][2] = ex2f(sacc[nb][2] - mn1);
            sacc[nb][3] = ex2f(sacc[nb][3] - mn1);
            rs0 += sacc[nb][0] + sacc[nb][1];
            rs1 += sacc[nb][2] + sacc[nb][3];
        }
        rs0 += __shfl_xor_sync(0xffffffffu, rs0, 1);
        rs0 += __shfl_xor_sync(0xffffffffu, rs0, 2);
        rs1 += __shfl_xor_sync(0xffffffffu, rs1, 1);
        rs1 += __shfl_xor_sync(0xffffffffu, rs1, 2);

        l0 = l0 * corr0 + rs0;
        l1 = l1 * corr1 + rs1;
        m0 = mn0;
        m1 = mn1;
#pragma unroll
        for (int db = 0; db < 8; db++) {
            oacc[db][0] *= corr0;
            oacc[db][1] *= corr0;
            oacc[db][2] *= corr1;
            oacc[db][3] *= corr1;
        }

#pragma unroll
        for (int ks = 0; ks < 4; ks++) {
            uint32_t ph[4], pl[4];
            packsplit2(sacc[2 * ks][0], sacc[2 * ks][1], ph[0], pl[0]);
            packsplit2(sacc[2 * ks][2], sacc[2 * ks][3], ph[1], pl[1]);
            packsplit2(sacc[2 * ks + 1][0], sacc[2 * ks + 1][1], ph[2], pl[2]);
            packsplit2(sacc[2 * ks + 1][2], sacc[2 * ks + 1][3], ph[3], pl[3]);
            const int kb = ks * 32;
#pragma unroll
            for (int db = 0; db < 8; db++) {
                const int vo = (db * 8 + g) * FRS + tig * 4 + kb;
                uint32_t vh0 = *(const uint32_t*)(buf + OFF_VTH + vo);
                uint32_t vh1 = *(const uint32_t*)(buf + OFF_VTH + vo + 16);
                uint32_t vl0 = *(const uint32_t*)(buf + OFF_VTL + vo);
                uint32_t vl1 = *(const uint32_t*)(buf + OFF_VTL + vo + 16);
                mma_bf16(oacc[db], ph[0], ph[1], ph[2], ph[3], vh0, vh1);
                mma_bf16(oacc[db], ph[0], ph[1], ph[2], ph[3], vl0, vl1);
                mma_bf16(oacc[db], pl[0], pl[1], pl[2], pl[3], vh0, vh1);
            }
        }
    }

    // finalize: tf32-rounded y (proj A operand is pre-rounded for free)
    float inv0 = 1.0f / l0;
    float inv1 = 1.0f / l1;
    int b = bh >> 4;
    int h = bh & 15;
    int t0 = q0 + r0;
    int t1 = t0 + 8;
#pragma unroll
    for (int db = 0; db < 8; db++) {
        int col = h * 64 + db * 8 + 2 * tig;
        float2 y0 = make_float2(tf32f(oacc[db][0] * inv0), tf32f(oacc[db][1] * inv0));
        float2 y1 = make_float2(tf32f(oacc[db][2] * inv1), tf32f(oacc[db][3] * inv1));
        *(float2*)&g_y[(size_t)(b * TSEQ + t0) * CDIM + col] = y0;
        *(float2*)&g_y[(size_t)(b * TSEQ + t1) * CDIM + col] = y1;
    }
}

// ---------------------------------------------------------------------------
// Launch
// ---------------------------------------------------------------------------
extern "C" void kernel_launch(void* const* d_in, const int* in_sizes, int n_in,
                              void* d_out, int out_size) {
    const float* x      = (const float*)d_in[0];
    const float* w_attn = (const float*)d_in[1];
    const float* b_attn = (const float*)d_in[2];
    const float* w_proj = (const float*)d_in[3];
    const float* b_proj = (const float*)d_in[4];
    float* out = (float*)d_out;

    float *qkv, *y, *xt, *wat, *wpt;
    float2* rope;
    __nv_bfloat16 *qh, *ql, *kh, *kl, *vth, *vtl;
    cudaGetSymbolAddress((void**)&qkv, g_qkv);
    cudaGetSymbolAddress((void**)&xt, g_xt);
    cudaGetSymbolAddress((void**)&wat, g_wat);
    cudaGetSymbolAddress((void**)&wpt, g_wpt);
    cudaGetSymbolAddress((void**)&qh, g_qh);
    cudaGetSymbolAddress((void**)&ql, g_ql);
    cudaGetSymbolAddress((void**)&kh, g_kh);
    cudaGetSymbolAddress((void**)&kl, g_kl);
    cudaGetSymbolAddress((void**)&vth, g_vth);
    cudaGetSymbolAddress((void**)&vtl, g_vtl);
    cudaGetSymbolAddress((void**)&y, g_y);
    cudaGetSymbolAddress((void**)&rope, g_rope);

    cudaFuncSetAttribute(gemm_tf32_kernel,
                         cudaFuncAttributeMaxDynamicSharedMemorySize,
                         GEMM_SMEM_BYTES);
    cudaFuncSetAttribute(flash_mma_kernel,
                         cudaFuncAttributeMaxDynamicSharedMemorySize,
                         FLASH_SMEM_BYTES);

    build_rope_kernel<<<(TSEQ * 32 + 255) / 256, 256>>>(rope);

    // tf32 pre-round of GEMM operands
    cvt_tf32_kernel<<<(MROWS * CDIM / 4 + 255) / 256, 256>>>(x, xt,
                                                             MROWS * CDIM / 4);
    cvt_tf32_kernel<<<(CDIM * QKVCOLS / 4 + 255) / 256, 256>>>(
        w_attn, wat, CDIM * QKVCOLS / 4);
    cvt_tf32_kernel<<<(CDIM * CDIM / 4 + 255) / 256, 256>>>(w_proj, wpt,
                                                            CDIM * CDIM / 4);

    // QKV GEMM
    gemm_tf32_kernel<<<dim3(QKVCOLS / 128, MROWS / 128), 256, GEMM_SMEM_BYTES>>>(
        xt, wat, b_attn, qkv, MROWS, QKVCOLS, CDIM);

    // RoPE + scatter + splits + V transpose
    rope_scatter_split_kernel<<<dim3(TSEQ / 64, BSZ * NHEAD), 256>>>(
        qkv, rope, qh, ql, kh, kl, vth, vtl);

    // Flash attention
    flash_mma_kernel<<<dim3(TSEQ / 64, BSZ * NHEAD), 128, FLASH_SMEM_BYTES>>>(
        qh, ql, kh, kl, vth, vtl);

    // Output projection
    gemm_tf32_kernel<<<dim3(CDIM / 128, MROWS / 128), 256, GEMM_SMEM_BYTES>>>(
        y, wpt, b_proj, out, MROWS, CDIM, CDIM);
}

// round 8
// speedup vs baseline: 4.9991x; 1.0421x over previous
#include <cuda_runtime.h>
#include <cuda_bf16.h>
#include <math.h>
#include <math_constants.h>
#include <stdint.h>

// Problem constants
#define BSZ 2
#define TSEQ 2048
#define CDIM 1024
#define NHEAD 16
#define DHEAD 64
#define MROWS (BSZ * TSEQ)          // 4096
#define QKVCOLS (3 * CDIM)          // 3072

// ---------------------------------------------------------------------------
// Scratch
// ---------------------------------------------------------------------------
__device__ float g_qkv[(size_t)MROWS * QKVCOLS];
__device__ float g_xf[(size_t)MROWS * CDIM];          // x, A-fragment order, tf32
__device__ float g_waf[(size_t)CDIM * QKVCOLS];       // w_attn, B-frag order, tf32
__device__ float g_wpf[(size_t)CDIM * CDIM];          // w_proj, B-frag order, tf32
__device__ float g_yf[(size_t)MROWS * CDIM];          // y, A-fragment order, tf32
__device__ __nv_bfloat16 g_qh[(size_t)BSZ * NHEAD * TSEQ * DHEAD];
__device__ __nv_bfloat16 g_ql[(size_t)BSZ * NHEAD * TSEQ * DHEAD];
__device__ __nv_bfloat16 g_kh[(size_t)BSZ * NHEAD * TSEQ * DHEAD];
__device__ __nv_bfloat16 g_kl[(size_t)BSZ * NHEAD * TSEQ * DHEAD];
__device__ __nv_bfloat16 g_vth[(size_t)BSZ * NHEAD * DHEAD * TSEQ];  // [bh][d][t]
__device__ __nv_bfloat16 g_vtl[(size_t)BSZ * NHEAD * DHEAD * TSEQ];
__device__ float g_y[(size_t)MROWS * CDIM];
__device__ float2 g_rope[TSEQ * (DHEAD / 2)];

// ---------------------------------------------------------------------------
// RoPE table
// ---------------------------------------------------------------------------
__global__ void build_rope_kernel(float2* __restrict__ table) {
    int i = blockIdx.x * blockDim.x + threadIdx.x;
    if (i >= TSEQ * 32) return;
    int t = i >> 5;
    int j = i & 31;
    double inv = pow(10000.0, -(double)j / 32.0);
    double ang = (double)t * inv;
    table[i] = make_float2((float)cos(ang), (float)sin(ang));
}

// ---------------------------------------------------------------------------
// Math helpers
// ---------------------------------------------------------------------------
__device__ __forceinline__ uint32_t f2tf32(float x) {
    uint32_t r;
    asm("cvt.rna.tf32.f32 %0, %1;" : "=r"(r) : "f"(x));
    return r;
}
__device__ __forceinline__ float tf32f(float x) {
    return __uint_as_float(f2tf32(x));
}
__device__ __forceinline__ float ex2f(float x) {
    float r;
    asm("ex2.approx.ftz.f32 %0, %1;" : "=f"(r) : "f"(x));
    return r;
}
__device__ __forceinline__ void mma_tf32(float c[4], uint32_t a0, uint32_t a1,
                                         uint32_t a2, uint32_t a3,
                                         uint32_t b0, uint32_t b1) {
    asm volatile(
        "mma.sync.aligned.m16n8k8.row.col.f32.tf32.tf32.f32 "
        "{%0,%1,%2,%3}, {%4,%5,%6,%7}, {%8,%9}, {%0,%1,%2,%3};\n"
        : "+f"(c[0]), "+f"(c[1]), "+f"(c[2]), "+f"(c[3])
        : "r"(a0), "r"(a1), "r"(a2), "r"(a3), "r"(b0), "r"(b1));
}
__device__ __forceinline__ void mma_bf16(float c[4], uint32_t a0, uint32_t a1,
                                         uint32_t a2, uint32_t a3,
                                         uint32_t b0, uint32_t b1) {
    asm volatile(
        "mma.sync.aligned.m16n8k16.row.col.f32.bf16.bf16.f32 "
        "{%0,%1,%2,%3}, {%4,%5,%6,%7}, {%8,%9}, {%0,%1,%2,%3};\n"
        : "+f"(c[0]), "+f"(c[1]), "+f"(c[2]), "+f"(c[3])
        : "r"(a0), "r"(a1), "r"(a2), "r"(a3), "r"(b0), "r"(b1));
}
__device__ __forceinline__ void packsplit2(float p0, float p1,
                                           uint32_t& hi, uint32_t& lo) {
    __nv_bfloat162 h = __floats2bfloat162_rn(p0, p1);
    float2 f = __bfloat1622float2(h);
    __nv_bfloat162 l = __floats2bfloat162_rn(p0 - f.x, p1 - f.y);
    hi = *reinterpret_cast<uint32_t*>(&h);
    lo = *reinterpret_cast<uint32_t*>(&l);
}
__device__ __forceinline__ uint32_t smem_u32(const void* p) {
    uint32_t a;
    asm("{ .reg .u64 t; cvta.to.shared.u64 t, %1; cvt.u32.u64 %0, t; }"
        : "=r"(a) : "l"(p));
    return a;
}
__device__ __forceinline__ void cp16(uint32_t smem, const void* g) {
    asm volatile("cp.async.ca.shared.global [%0], [%1], 16;"
                 :: "r"(smem), "l"(g) : "memory");
}
#define CP_COMMIT() asm volatile("cp.async.commit_group;" ::: "memory")
#define CP_WAIT0() asm volatile("cp.async.wait_group 0;" ::: "memory")
#define CP_WAIT1() asm volatile("cp.async.wait_group 1;" ::: "memory")

// ---------------------------------------------------------------------------
// A-fragment reorder + tf32 round: in [M][K] row-major ->
// out [M/16][K/8][32][4]: lane (g,tig) holds {A[g][tig], A[g+8][tig],
// A[g][tig+4], A[g+8][tig+4]} of its 16x8 block.
// ---------------------------------------------------------------------------
__global__ void afrag_kernel(const float* __restrict__ in,
                             float* __restrict__ out, int K) {
    int idx = blockIdx.x * 256 + threadIdx.x;
    int lane = idx & 31;
    int blk = idx >> 5;                 // rb * (K/8) + cb
    int KB = K >> 3;
    int cb = blk % KB, rb = blk / KB;
    int g = lane >> 2, tig = lane & 3;
    const float* p = in + (size_t)(rb * 16 + g) * K + cb * 8 + tig;
    float4 v;
    v.x = tf32f(p[0]);
    v.y = tf32f(p[(size_t)8 * K]);
    v.z = tf32f(p[4]);
    v.w = tf32f(p[(size_t)8 * K + 4]);
    ((float4*)out)[idx] = v;
}

// ---------------------------------------------------------------------------
// B-fragment reorder + tf32 round: in [K][N] row-major ->
// out [K/8][N/8][32][2]: lane (g,tig) holds {B[tig][g], B[tig+4][g]}.
// ---------------------------------------------------------------------------
__global__ void bfrag_kernel(const float* __restrict__ in,
                             float* __restrict__ out, int N) {
    int idx = blockIdx.x * 256 + threadIdx.x;
    int lane = idx & 31;
    int blk = idx >> 5;                 // kb * (N/8) + nb
    int NB = N >> 3;
    int nb = blk % NB, kb = blk / NB;
    int g = lane >> 2, tig = lane & 3;
    const float* p = in + (size_t)(kb * 8 + tig) * N + nb * 8 + g;
    float2 v;
    v.x = tf32f(p[0]);
    v.y = tf32f(p[(size_t)4 * N]);
    ((float2*)out)[idx] = v;
}

// ---------------------------------------------------------------------------
// TF32 GEMM v3: fragment-order operands, cp.async 2-stage pipeline.
// C[M,N] = A@B + bias. 128x128x32 tile, 256 thr (8 warps, 2m x 4n).
// Smem: A tile 16KB [8 rblk][4 kblk][32][4], B tile 16KB [4 kblk][16 nblk][32][2]
// ---------------------------------------------------------------------------
#define GEMM_SMEM_BYTES 65536

__global__ __launch_bounds__(256, 2)
void gemm_tf32_kernel(const float* __restrict__ Af, const float* __restrict__ Bf,
                      const float* __restrict__ bias, float* __restrict__ C,
                      int M, int N, int K) {
    extern __shared__ float sm[];
    const uint32_t smb = smem_u32(sm);
    // byte offsets: A0 | A1 | B0 | B1 (16KB each)
    const int tid = threadIdx.x;
    const int lane = tid & 31;
    const int warp = tid >> 5;
    const int wm = warp >> 2;      // 0..1
    const int wn = warp & 3;       // 0..3
    const int g = lane >> 2;
    const int tig = lane & 3;
    const int row0 = blockIdx.y * 128;
    const int col0 = blockIdx.x * 128;
    const int KB = K >> 3;
    const int NB = N >> 3;
    const int rb0 = row0 >> 4;
    const int nb0 = col0 >> 3;

    float acc[4][4][4];
#pragma unroll
    for (int im = 0; im < 4; im++)
#pragma unroll
        for (int in = 0; in < 4; in++)
#pragma unroll
            for (int r = 0; r < 4; r++) acc[im][in][r] = 0.0f;

    // loader maps: 4 A-chunks + 4 B-chunks (16B each) per thread per stage
    int a_rblk[4], a_kblk[4], a_l16[4];
    int b_kblk[4], b_nblk[4], b_w16[4];
#pragma unroll
    for (int s = 0; s < 4; s++) {
        int c = tid + s * 256;          // 0..1023
        int ablk = c >> 5;
        a_rblk[s] = ablk >> 2;
        a_kblk[s] = ablk & 3;
        a_l16[s] = c & 31;
        int bblk = c >> 4;
        b_kblk[s] = bblk >> 4;
        b_nblk[s] = bblk & 15;
        b_w16[s] = c & 15;
    }

    const int nT = K / 32;

    // prologue: stage 0 (kb0 = 0)
#pragma unroll
    for (int s = 0; s < 4; s++) {
        cp16(smb + (uint32_t)((a_rblk[s] * 4 + a_kblk[s]) * 512 + a_l16[s] * 16),
             Af + (((size_t)(rb0 + a_rblk[s]) * KB + a_kblk[s]) << 7) + a_l16[s] * 4);
        cp16(smb + 32768u + (uint32_t)((b_kblk[s] * 16 + b_nblk[s]) * 256 + b_w16[s] * 16),
             Bf + (((size_t)b_kblk[s] * NB + nb0 + b_nblk[s]) << 6) + b_w16[s] * 4);
    }
    CP_COMMIT();

    for (int t = 0; t < nT; t++) {
        if (t + 1 < nT) {
            const int kb = (t + 1) * 4;
            const uint32_t ao = ((t + 1) & 1) ? 16384u : 0u;
            const uint32_t bo = 32768u + (((t + 1) & 1) ? 16384u : 0u);
#pragma unroll
            for (int s = 0; s < 4; s++) {
                cp16(smb + ao + (uint32_t)((a_rblk[s] * 4 + a_kblk[s]) * 512 + a_l16[s] * 16),
                     Af + (((size_t)(rb0 + a_rblk[s]) * KB + kb + a_kblk[s]) << 7) + a_l16[s] * 4);
                cp16(smb + bo + (uint32_t)((b_kblk[s] * 16 + b_nblk[s]) * 256 + b_w16[s] * 16),
                     Bf + (((size_t)(kb + b_kblk[s]) * NB + nb0 + b_nblk[s]) << 6) + b_w16[s] * 4);
            }
            CP_COMMIT();
            CP_WAIT1();
        } else {
            CP_WAIT0();
        }
        __syncthreads();

        const float* As = sm + (t & 1) * 4096;
        const float* Bs = sm + 8192 + (t & 1) * 4096;

#pragma unroll
        for (int kk = 0; kk < 4; kk++) {
            float4 af[4];
#pragma unroll
            for (int im = 0; im < 4; im++)
                af[im] = *(const float4*)(As + ((wm * 4 + im) * 4 + kk) * 128 + lane * 4);
            float2 bf[4];
#pragma unroll
            for (int in = 0; in < 4; in++)
                bf[in] = *(const float2*)(Bs + (kk * 16 + wn * 4 + in) * 64 + lane * 2);
#pragma unroll
            for (int im = 0; im < 4; im++)
#pragma unroll
                for (int in = 0; in < 4; in++)
                    mma_tf32(acc[im][in],
                             __float_as_uint(af[im].x), __float_as_uint(af[im].y),
                             __float_as_uint(af[im].z), __float_as_uint(af[im].w),
                             __float_as_uint(bf[in].x), __float_as_uint(bf[in].y));
        }
        __syncthreads();
    }

    // epilogue: rows g + {0,8}, cols 2*tig + {0,1}
#pragma unroll
    for (int im = 0; im < 4; im++) {
        int r = row0 + wm * 64 + im * 16 + g;
#pragma unroll
        for (int in = 0; in < 4; in++) {
            int c = col0 + wn * 32 + in * 8 + tig * 2;
            float b0 = bias[c], b1 = bias[c + 1];
            float2 v0 = make_float2(acc[im][in][0] + b0, acc[im][in][1] + b1);
            float2 v1 = make_float2(acc[im][in][2] + b0, acc[im][in][3] + b1);
            *(float2*)&C[(size_t)r * N + c] = v0;
            *(float2*)&C[(size_t)(r + 8) * N + c] = v1;
        }
    }
}

// ---------------------------------------------------------------------------
// RoPE + scatter + splits + V transpose (unchanged)
// ---------------------------------------------------------------------------
__global__ __launch_bounds__(256)
void rope_scatter_split_kernel(const float* __restrict__ qkv,
                               const float2* __restrict__ rope,
                               __nv_bfloat16* __restrict__ qh,
                               __nv_bfloat16* __restrict__ ql,
                               __nv_bfloat16* __restrict__ kh,
                               __nv_bfloat16* __restrict__ kl,
                               __nv_bfloat16* __restrict__ vth,
                               __nv_bfloat16* __restrict__ vtl) {
    __shared__ __nv_bfloat16 vsh[64][66];
    __shared__ __nv_bfloat16 vsl[64][66];

    int bh = blockIdx.y;
    int tb = blockIdx.x * 64;
    int b = bh >> 4;
    int h = bh & 15;
    int tid = threadIdx.x;

    const float SCL = 0.125f * 1.4426950408889634f;

#pragma unroll
    for (int e = 0; e < 16; e++) {
        int idx = tid + e * 256;
        int tl = idx >> 6;
        int d = idx & 63;
        int t = tb + tl;
        size_t base = (size_t)(b * TSEQ + t) * QKVCOLS + h * DHEAD;
        float2 cs = rope[t * 32 + (d & 31)];

        float qv = qkv[base + d];
        float kv = qkv[base + CDIM + d];
        float vv = qkv[base + 2 * CDIM + d];
        int dp = (d < 32) ? d + 32 : d - 32;
        float sgn = (d < 32) ? -1.0f : 1.0f;
        float qr = qkv[base + dp];
        float kr = qkv[base + CDIM + dp];

        float qrot = (qv * cs.x + sgn * qr * cs.y) * SCL;
        float krot = kv * cs.x + sgn * kr * cs.y;

        size_t o = ((size_t)bh * TSEQ + t) * DHEAD + d;
        __nv_bfloat16 qhv = __float2bfloat16(qrot);
        __nv_bfloat16 khv = __float2bfloat16(krot);
        qh[o] = qhv;
        ql[o] = __float2bfloat16(qrot - __bfloat162float(qhv));
        kh[o] = khv;
        kl[o] = __float2bfloat16(krot - __bfloat162float(khv));

        __nv_bfloat16 vhv = __float2bfloat16(vv);
        vsh[d][tl] = vhv;
        vsl[d][tl] = __float2bfloat16(vv - __bfloat162float(vhv));
    }
    __syncthreads();
#pragma unroll
    for (int e = 0; e < 16; e++) {
        int idx = tid + e * 256;
        int d = idx >> 6;
        int tl = idx & 63;
        size_t o = ((size_t)bh * DHEAD + d) * TSEQ + tb + tl;
        vth[o] = vsh[d][tl];
        vtl[o] = vsl[d][tl];
    }
}

// ---------------------------------------------------------------------------
// Flash attention v3 (round 6/7, unchanged; epilogue writes plain floats)
// ---------------------------------------------------------------------------
#define FRS 144
#define OFF_KH 0
#define OFF_KL 9216
#define OFF_VTH 18432
#define OFF_VTL 27648
#define BUFB 36864
#define FLASH_SMEM_BYTES (2 * BUFB)

#define NEGBIG (-1e30f)

__global__ __launch_bounds__(128, 3)
void flash_mma_kernel(const __nv_bfloat16* __restrict__ QH,
                      const __nv_bfloat16* __restrict__ QL,
                      const __nv_bfloat16* __restrict__ KH,
                      const __nv_bfloat16* __restrict__ KL,
                      const __nv_bfloat16* __restrict__ VTH,
                      const __nv_bfloat16* __restrict__ VTL) {
    extern __shared__ char smc[];
    const uint32_t smb = smem_u32(smc);

    int bh = blockIdx.y;
    int qt = gridDim.x - 1 - blockIdx.x;
    int q0 = qt * 64;

    int tid = threadIdx.x;
    int lane = tid & 31;
    int w = tid >> 5;
    int g = lane >> 2;
    int tig = lane & 3;
    const int r0 = w * 16 + g;

    const __nv_bfloat16* KHg = KH + (size_t)bh * TSEQ * DHEAD;
    const __nv_bfloat16* KLg = KL + (size_t)bh * TSEQ * DHEAD;
    const __nv_bfloat16* VTHg = VTH + (size_t)bh * DHEAD * TSEQ;
    const __nv_bfloat16* VTLg = VTL + (size_t)bh * DHEAD * TSEQ;

    {
#pragma unroll
        for (int s = 0; s < 4; s++) {
            int f = tid + s * 128;
            int r = f >> 3;
            int c = (f & 7) * 8;
            uint32_t ro = (uint32_t)(r * FRS + c * 2);
            cp16(smb + OFF_KH + ro, KHg + (size_t)r * DHEAD + c);
            cp16(smb + OFF_KL + ro, KLg + (size_t)r * DHEAD + c);
            cp16(smb + OFF_VTH + ro, VTHg + (size_t)r * TSEQ + c);
            cp16(smb + OFF_VTL + ro, VTLg + (size_t)r * TSEQ + c);
        }
        CP_COMMIT();
    }

    uint32_t qah[4][4], qal[4][4];
    {
        const __nv_bfloat16* Qhg = QH + ((size_t)bh * TSEQ + q0 + r0) * DHEAD;
        const __nv_bfloat16* Qlg = QL + ((size_t)bh * TSEQ + q0 + r0) * DHEAD;
#pragma unroll
        for (int ks = 0; ks < 4; ks++) {
            int c0 = ks * 16 + 2 * tig;
            qah[ks][0] = *(const uint32_t*)(Qhg + c0);
            qah[ks][1] = *(const uint32_t*)(Qhg + 8 * DHEAD + c0);
            qah[ks][2] = *(const uint32_t*)(Qhg + c0 + 8);
            qah[ks][3] = *(const uint32_t*)(Qhg + 8 * DHEAD + c0 + 8);
            qal[ks][0] = *(const uint32_t*)(Qlg + c0);
            qal[ks][1] = *(const uint32_t*)(Qlg + 8 * DHEAD + c0);
            qal[ks][2] = *(const uint32_t*)(Qlg + c0 + 8);
            qal[ks][3] = *(const uint32_t*)(Qlg + 8 * DHEAD + c0 + 8);
        }
    }

    float oacc[8][4];
#pragma unroll
    for (int db = 0; db < 8; db++)
#pragma unroll
        for (int r = 0; r < 4; r++) oacc[db][r] = 0.0f;
    float m0 = NEGBIG, m1 = NEGBIG, l0 = 0.0f, l1 = 0.0f;

    for (int jt = 0; jt <= qt; jt++) {
        CP_WAIT0();
        __syncthreads();

        if (jt < qt) {
            int k0n = (jt + 1) * 64;
            uint32_t nb_ = smb + ((jt + 1) & 1) * BUFB;
#pragma unroll
            for (int s = 0; s < 4; s++) {
                int f = tid + s * 128;
                int r = f >> 3;
                int c = (f & 7) * 8;
                uint32_t ro = (uint32_t)(r * FRS + c * 2);
                cp16(nb_ + OFF_KH + ro, KHg + (size_t)(k0n + r) * DHEAD + c);
                cp16(nb_ + OFF_KL + ro, KLg + (size_t)(k0n + r) * DHEAD + c);
                cp16(nb_ + OFF_VTH + ro, VTHg + (size_t)r * TSEQ + k0n + c);
                cp16(nb_ + OFF_VTL + ro, VTLg + (size_t)r * TSEQ + k0n + c);
            }
            CP_COMMIT();
        }

        const char* buf = smc + (jt & 1) * BUFB;

        float sacc[8][4];
#pragma unroll
        for (int nb = 0; nb < 8; nb++)
#pragma unroll
            for (int r = 0; r < 4; r++) sacc[nb][r] = 0.0f;

#pragma unroll
        for (int ks = 0; ks < 4; ks++) {
            const int kb = ks * 32;
#pragma unroll
            for (int nb = 0; nb < 8; nb++) {
                const int bo = (nb * 8 + g) * FRS + tig * 4 + kb;
                uint32_t bh0 = *(const uint32_t*)(buf + OFF_KH + bo);
                uint32_t bh1 = *(const uint32_t*)(buf + OFF_KH + bo + 16);
                uint32_t bl0 = *(const uint32_t*)(buf + OFF_KL + bo);
                uint32_t bl1 = *(const uint32_t*)(buf + OFF_KL + bo + 16);
                mma_bf16(sacc[nb], qah[ks][0], qah[ks][1], qah[ks][2], qah[ks][3], bh0, bh1);
                mma_bf16(sacc[nb], qah[ks][0], qah[ks][1], qah[ks][2], qah[ks][3], bl0, bl1);
                mma_bf16(sacc[nb], qal[ks][0], qal[ks][1], qal[ks][2], qal[ks][3], bh0, bh1);
            }
        }

        if (jt == qt) {
#pragma unroll
            for (int nb = 0; nb < 8; nb++) {
                int c0 = nb * 8 + 2 * tig;
#pragma unroll
                for (int e = 0; e < 2; e++) {
                    if (c0 + e > r0) sacc[nb][e] = NEGBIG;
                    if (c0 + e > r0 + 8) sacc[nb][2 + e] = NEGBIG;
                }
            }
        }

        float tm0 = NEGBIG, tm1 = NEGBIG;
#pragma unroll
        for (int nb = 0; nb < 8; nb++) {
            tm0 = fmaxf(tm0, fmaxf(sacc[nb][0], sacc[nb][1]));
            tm1 = fmaxf(tm1, fmaxf(sacc[nb][2], sacc[nb][3]));
        }
        tm0 = fmaxf(tm0, __shfl_xor_sync(0xffffffffu, tm0, 1));
        tm0 = fmaxf(tm0, __shfl_xor_sync(0xffffffffu, tm0, 2));
        tm1 = fmaxf(tm1, __shfl_xor_sync(0xffffffffu, tm1, 1));
        tm1 = fmaxf(tm1, __shfl_xor_sync(0xffffffffu, tm1, 2));

        float mn0 = fmaxf(m0, tm0);
        float mn1 = fmaxf(m1, tm1);
        float corr0 = ex2f(m0 - mn0);
        float corr1 = ex2f(m1 - mn1);
        float rs0 = 0.0f, rs1 = 0.0f;
#pragma unroll
        for (int nb = 0; nb < 8; nb++) {
            sacc[nb][0] = ex2f(sacc[nb][0] - mn0);
            sacc[nb][1] = ex2f(sacc[nb][1] - mn0);
            sacc[nb][2] = ex2f(sacc[nb][2] - mn1);
            sacc[nb][3] = ex2f(sacc[nb][3] - mn1);
            rs0 += sacc[nb][0] + sacc[nb][1];
            rs1 += sacc[nb][2] + sacc[nb][3];
        }
        rs0 += __shfl_xor_sync(0xffffffffu, rs0, 1);
        rs0 += __shfl_xor_sync(0xffffffffu, rs0, 2);
        rs1 += __shfl_xor_sync(0xffffffffu, rs1, 1);
        rs1 += __shfl_xor_sync(0xffffffffu, rs1, 2);

        l0 = l0 * corr0 + rs0;
        l1 = l1 * corr1 + rs1;
        m0 = mn0;
        m1 = mn1;
#pragma unroll
        for (int db = 0; db < 8; db++) {
            oacc[db][0] *= corr0;
            oacc[db][1] *= corr0;
            oacc[db][2] *= corr1;
            oacc[db][3] *= corr1;
        }

#pragma unroll
        for (int ks = 0; ks < 4; ks++) {
            uint32_t ph[4], pl[4];
            packsplit2(sacc[2 * ks][0], sacc[2 * ks][1], ph[0], pl[0]);
            packsplit2(sacc[2 * ks][2], sacc[2 * ks][3], ph[1], pl[1]);
            packsplit2(sacc[2 * ks + 1][0], sacc[2 * ks + 1][1], ph[2], pl[2]);
            packsplit2(sacc[2 * ks + 1][2], sacc[2 * ks + 1][3], ph[3], pl[3]);
            const int kb = ks * 32;
#pragma unroll
            for (int db = 0; db < 8; db++) {
                const int vo = (db * 8 + g) * FRS + tig * 4 + kb;
                uint32_t vh0 = *(const uint32_t*)(buf + OFF_VTH + vo);
                uint32_t vh1 = *(const uint32_t*)(buf + OFF_VTH + vo + 16);
                uint32_t vl0 = *(const uint32_t*)(buf + OFF_VTL + vo);
                uint32_t vl1 = *(const uint32_t*)(buf + OFF_VTL + vo + 16);
                mma_bf16(oacc[db], ph[0], ph[1], ph[2], ph[3], vh0, vh1);
                mma_bf16(oacc[db], ph[0], ph[1], ph[2], ph[3], vl0, vl1);
                mma_bf16(oacc[db], pl[0], pl[1], pl[2], pl[3], vh0, vh1);
            }
        }
    }

    float inv0 = 1.0f / l0;
    float inv1 = 1.0f / l1;
    int b = bh >> 4;
    int h = bh & 15;
    int t0 = q0 + r0;
    int t1 = t0 + 8;
#pragma unroll
    for (int db = 0; db < 8; db++) {
        int col = h * 64 + db * 8 + 2 * tig;
        float2 y0 = make_float2(oacc[db][0] * inv0, oacc[db][1] * inv0);
        float2 y1 = make_float2(oacc[db][2] * inv1, oacc[db][3] * inv1);
        *(float2*)&g_y[(size_t)(b * TSEQ + t0) * CDIM + col] = y0;
        *(float2*)&g_y[(size_t)(b * TSEQ + t1) * CDIM + col] = y1;
    }
}

// ---------------------------------------------------------------------------
// Launch
// ---------------------------------------------------------------------------
extern "C" void kernel_launch(void* const* d_in, const int* in_sizes, int n_in,
                              void* d_out, int out_size) {
    const float* x      = (const float*)d_in[0];
    const float* w_attn = (const float*)d_in[1];
    const float* b_attn = (const float*)d_in[2];
    const float* w_proj = (const float*)d_in[3];
    const float* b_proj = (const float*)d_in[4];
    float* out = (float*)d_out;

    float *qkv, *y, *xf, *waf, *wpf, *yf;
    float2* rope;
    __nv_bfloat16 *qh, *ql, *kh, *kl, *vth, *vtl;
    cudaGetSymbolAddress((void**)&qkv, g_qkv);
    cudaGetSymbolAddress((void**)&xf, g_xf);
    cudaGetSymbolAddress((void**)&waf, g_waf);
    cudaGetSymbolAddress((void**)&wpf, g_wpf);
    cudaGetSymbolAddress((void**)&yf, g_yf);
    cudaGetSymbolAddress((void**)&qh, g_qh);
    cudaGetSymbolAddress((void**)&ql, g_ql);
    cudaGetSymbolAddress((void**)&kh, g_kh);
    cudaGetSymbolAddress((void**)&kl, g_kl);
    cudaGetSymbolAddress((void**)&vth, g_vth);
    cudaGetSymbolAddress((void**)&vtl, g_vtl);
    cudaGetSymbolAddress((void**)&y, g_y);
    cudaGetSymbolAddress((void**)&rope, g_rope);

    cudaFuncSetAttribute(gemm_tf32_kernel,
                         cudaFuncAttributeMaxDynamicSharedMemorySize,
                         GEMM_SMEM_BYTES);
    cudaFuncSetAttribute(flash_mma_kernel,
                         cudaFuncAttributeMaxDynamicSharedMemorySize,
                         FLASH_SMEM_BYTES);

    build_rope_kernel<<<(TSEQ * 32 + 255) / 256, 256>>>(rope);

    // fragment-order prep (tf32 rounding fused)
    afrag_kernel<<<(MROWS / 16) * (CDIM / 8) * 32 / 256, 256>>>(x, xf, CDIM);
    bfrag_kernel<<<(CDIM / 8) * (QKVCOLS / 8) * 32 / 256, 256>>>(w_attn, waf, QKVCOLS);
    bfrag_kernel<<<(CDIM / 8) * (CDIM / 8) * 32 / 256, 256>>>(w_proj, wpf, CDIM);

    // QKV GEMM
    gemm_tf32_kernel<<<dim3(QKVCOLS / 128, MROWS / 128), 256, GEMM_SMEM_BYTES>>>(
        xf, waf, b_attn, qkv, MROWS, QKVCOLS, CDIM);

    // RoPE + scatter + splits + V transpose
    rope_scatter_split_kernel<<<dim3(TSEQ / 64, BSZ * NHEAD), 256>>>(
        qkv, rope, qh, ql, kh, kl, vth, vtl);

    // Flash attention
    flash_mma_kernel<<<dim3(TSEQ / 64, BSZ * NHEAD), 128, FLASH_SMEM_BYTES>>>(
        qh, ql, kh, kl, vth, vtl);

    // y -> fragment order, then output projection
    afrag_kernel<<<(MROWS / 16) * (CDIM / 8) * 32 / 256, 256>>>(y, yf, CDIM);
    gemm_tf32_kernel<<<dim3(CDIM / 128, MROWS / 128), 256, GEMM_SMEM_BYTES>>>(
        yf, wpf, b_proj, out, MROWS, CDIM, CDIM);
}

// round 9
// speedup vs baseline: 5.0940x; 1.0190x over previous
#include <cuda_runtime.h>
#include <cuda_bf16.h>
#include <math.h>
#include <math_constants.h>
#include <stdint.h>

// Problem constants
#define BSZ 2
#define TSEQ 2048
#define CDIM 1024
#define NHEAD 16
#define DHEAD 64
#define MROWS (BSZ * TSEQ)          // 4096
#define QKVCOLS (3 * CDIM)          // 3072

// ---------------------------------------------------------------------------
// Scratch
// ---------------------------------------------------------------------------
__device__ float g_qkv[(size_t)MROWS * QKVCOLS];
__device__ float g_xf[(size_t)MROWS * CDIM];          // x, A-fragment order, tf32
__device__ float g_waf[(size_t)CDIM * QKVCOLS];       // w_attn, B-frag order, tf32
__device__ float g_wpf[(size_t)CDIM * CDIM];          // w_proj, B-frag order, tf32
__device__ float g_yf[(size_t)MROWS * CDIM];          // y, A-fragment order, tf32
__device__ __nv_bfloat16 g_qh[(size_t)BSZ * NHEAD * TSEQ * DHEAD];
__device__ __nv_bfloat16 g_ql[(size_t)BSZ * NHEAD * TSEQ * DHEAD];
__device__ __nv_bfloat16 g_kh[(size_t)BSZ * NHEAD * TSEQ * DHEAD];
__device__ __nv_bfloat16 g_kl[(size_t)BSZ * NHEAD * TSEQ * DHEAD];
__device__ __nv_bfloat16 g_vth[(size_t)BSZ * NHEAD * DHEAD * TSEQ];  // [bh][d][t]
__device__ __nv_bfloat16 g_vtl[(size_t)BSZ * NHEAD * DHEAD * TSEQ];
__device__ float g_y[(size_t)MROWS * CDIM];
__device__ float2 g_rope[TSEQ * (DHEAD / 2)];

// ---------------------------------------------------------------------------
// RoPE table
// ---------------------------------------------------------------------------
__global__ void build_rope_kernel(float2* __restrict__ table) {
    int i = blockIdx.x * blockDim.x + threadIdx.x;
    if (i >= TSEQ * 32) return;
    int t = i >> 5;
    int j = i & 31;
    double inv = pow(10000.0, -(double)j / 32.0);
    double ang = (double)t * inv;
    table[i] = make_float2((float)cos(ang), (float)sin(ang));
}

// ---------------------------------------------------------------------------
// Math helpers
// ---------------------------------------------------------------------------
__device__ __forceinline__ uint32_t f2tf32(float x) {
    uint32_t r;
    asm("cvt.rna.tf32.f32 %0, %1;" : "=r"(r) : "f"(x));
    return r;
}
__device__ __forceinline__ float tf32f(float x) {
    return __uint_as_float(f2tf32(x));
}
__device__ __forceinline__ float ex2f(float x) {
    float r;
    asm("ex2.approx.ftz.f32 %0, %1;" : "=f"(r) : "f"(x));
    return r;
}
__device__ __forceinline__ void mma_tf32(float c[4], uint32_t a0, uint32_t a1,
                                         uint32_t a2, uint32_t a3,
                                         uint32_t b0, uint32_t b1) {
    asm volatile(
        "mma.sync.aligned.m16n8k8.row.col.f32.tf32.tf32.f32 "
        "{%0,%1,%2,%3}, {%4,%5,%6,%7}, {%8,%9}, {%0,%1,%2,%3};\n"
        : "+f"(c[0]), "+f"(c[1]), "+f"(c[2]), "+f"(c[3])
        : "r"(a0), "r"(a1), "r"(a2), "r"(a3), "r"(b0), "r"(b1));
}
__device__ __forceinline__ void mma_bf16(float c[4], uint32_t a0, uint32_t a1,
                                         uint32_t a2, uint32_t a3,
                                         uint32_t b0, uint32_t b1) {
    asm volatile(
        "mma.sync.aligned.m16n8k16.row.col.f32.bf16.bf16.f32 "
        "{%0,%1,%2,%3}, {%4,%5,%6,%7}, {%8,%9}, {%0,%1,%2,%3};\n"
        : "+f"(c[0]), "+f"(c[1]), "+f"(c[2]), "+f"(c[3])
        : "r"(a0), "r"(a1), "r"(a2), "r"(a3), "r"(b0), "r"(b1));
}
__device__ __forceinline__ void ldsm_x4(uint32_t& r0, uint32_t& r1,
                                        uint32_t& r2, uint32_t& r3,
                                        uint32_t addr) {
    asm volatile(
        "ldmatrix.sync.aligned.m8n8.x4.shared.b16 {%0,%1,%2,%3}, [%4];"
        : "=r"(r0), "=r"(r1), "=r"(r2), "=r"(r3) : "r"(addr));
}
__device__ __forceinline__ void packsplit2(float p0, float p1,
                                           uint32_t& hi, uint32_t& lo) {
    __nv_bfloat162 h = __floats2bfloat162_rn(p0, p1);
    float2 f = __bfloat1622float2(h);
    __nv_bfloat162 l = __floats2bfloat162_rn(p0 - f.x, p1 - f.y);
    hi = *reinterpret_cast<uint32_t*>(&h);
    lo = *reinterpret_cast<uint32_t*>(&l);
}
__device__ __forceinline__ uint32_t smem_u32(const void* p) {
    uint32_t a;
    asm("{ .reg .u64 t; cvta.to.shared.u64 t, %1; cvt.u32.u64 %0, t; }"
        : "=r"(a) : "l"(p));
    return a;
}
__device__ __forceinline__ void cp16(uint32_t smem, const void* g) {
    asm volatile("cp.async.ca.shared.global [%0], [%1], 16;"
                 :: "r"(smem), "l"(g) : "memory");
}
#define CP_COMMIT() asm volatile("cp.async.commit_group;" ::: "memory")
#define CP_WAIT0() asm volatile("cp.async.wait_group 0;" ::: "memory")
#define CP_WAIT1() asm volatile("cp.async.wait_group 1;" ::: "memory")

// ---------------------------------------------------------------------------
// A-fragment reorder + tf32 round (unchanged)
// ---------------------------------------------------------------------------
__global__ void afrag_kernel(const float* __restrict__ in,
                             float* __restrict__ out, int K) {
    int idx = blockIdx.x * 256 + threadIdx.x;
    int lane = idx & 31;
    int blk = idx >> 5;
    int KB = K >> 3;
    int cb = blk % KB, rb = blk / KB;
    int g = lane >> 2, tig = lane & 3;
    const float* p = in + (size_t)(rb * 16 + g) * K + cb * 8 + tig;
    float4 v;
    v.x = tf32f(p[0]);
    v.y = tf32f(p[(size_t)8 * K]);
    v.z = tf32f(p[4]);
    v.w = tf32f(p[(size_t)8 * K + 4]);
    ((float4*)out)[idx] = v;
}

// ---------------------------------------------------------------------------
// B-fragment reorder + tf32 round (unchanged)
// ---------------------------------------------------------------------------
__global__ void bfrag_kernel(const float* __restrict__ in,
                             float* __restrict__ out, int N) {
    int idx = blockIdx.x * 256 + threadIdx.x;
    int lane = idx & 31;
    int blk = idx >> 5;
    int NB = N >> 3;
    int nb = blk % NB, kb = blk / NB;
    int g = lane >> 2, tig = lane & 3;
    const float* p = in + (size_t)(kb * 8 + tig) * N + nb * 8 + g;
    float2 v;
    v.x = tf32f(p[0]);
    v.y = tf32f(p[(size_t)4 * N]);
    ((float2*)out)[idx] = v;
}

// ---------------------------------------------------------------------------
// TF32 GEMM v3 (unchanged from round 8)
// ---------------------------------------------------------------------------
#define GEMM_SMEM_BYTES 65536

__global__ __launch_bounds__(256, 2)
void gemm_tf32_kernel(const float* __restrict__ Af, const float* __restrict__ Bf,
                      const float* __restrict__ bias, float* __restrict__ C,
                      int M, int N, int K) {
    extern __shared__ float sm[];
    const uint32_t smb = smem_u32(sm);
    const int tid = threadIdx.x;
    const int lane = tid & 31;
    const int warp = tid >> 5;
    const int wm = warp >> 2;
    const int wn = warp & 3;
    const int g = lane >> 2;
    const int tig = lane & 3;
    const int row0 = blockIdx.y * 128;
    const int col0 = blockIdx.x * 128;
    const int KB = K >> 3;
    const int NB = N >> 3;
    const int rb0 = row0 >> 4;
    const int nb0 = col0 >> 3;

    float acc[4][4][4];
#pragma unroll
    for (int im = 0; im < 4; im++)
#pragma unroll
        for (int in = 0; in < 4; in++)
#pragma unroll
            for (int r = 0; r < 4; r++) acc[im][in][r] = 0.0f;

    int a_rblk[4], a_kblk[4], a_l16[4];
    int b_kblk[4], b_nblk[4], b_w16[4];
#pragma unroll
    for (int s = 0; s < 4; s++) {
        int c = tid + s * 256;
        int ablk = c >> 5;
        a_rblk[s] = ablk >> 2;
        a_kblk[s] = ablk & 3;
        a_l16[s] = c & 31;
        int bblk = c >> 4;
        b_kblk[s] = bblk >> 4;
        b_nblk[s] = bblk & 15;
        b_w16[s] = c & 15;
    }

    const int nT = K / 32;

#pragma unroll
    for (int s = 0; s < 4; s++) {
        cp16(smb + (uint32_t)((a_rblk[s] * 4 + a_kblk[s]) * 512 + a_l16[s] * 16),
             Af + (((size_t)(rb0 + a_rblk[s]) * KB + a_kblk[s]) << 7) + a_l16[s] * 4);
        cp16(smb + 32768u + (uint32_t)((b_kblk[s] * 16 + b_nblk[s]) * 256 + b_w16[s] * 16),
             Bf + (((size_t)b_kblk[s] * NB + nb0 + b_nblk[s]) << 6) + b_w16[s] * 4);
    }
    CP_COMMIT();

    for (int t = 0; t < nT; t++) {
        if (t + 1 < nT) {
            const int kb = (t + 1) * 4;
            const uint32_t ao = ((t + 1) & 1) ? 16384u : 0u;
            const uint32_t bo = 32768u + (((t + 1) & 1) ? 16384u : 0u);
#pragma unroll
            for (int s = 0; s < 4; s++) {
                cp16(smb + ao + (uint32_t)((a_rblk[s] * 4 + a_kblk[s]) * 512 + a_l16[s] * 16),
                     Af + (((size_t)(rb0 + a_rblk[s]) * KB + kb + a_kblk[s]) << 7) + a_l16[s] * 4);
                cp16(smb + bo + (uint32_t)((b_kblk[s] * 16 + b_nblk[s]) * 256 + b_w16[s] * 16),
                     Bf + (((size_t)(kb + b_kblk[s]) * NB + nb0 + b_nblk[s]) << 6) + b_w16[s] * 4);
            }
            CP_COMMIT();
            CP_WAIT1();
        } else {
            CP_WAIT0();
        }
        __syncthreads();

        const float* As = sm + (t & 1) * 4096;
        const float* Bs = sm + 8192 + (t & 1) * 4096;

#pragma unroll
        for (int kk = 0; kk < 4; kk++) {
            float4 af[4];
#pragma unroll
            for (int im = 0; im < 4; im++)
                af[im] = *(const float4*)(As + ((wm * 4 + im) * 4 + kk) * 128 + lane * 4);
            float2 bf[4];
#pragma unroll
            for (int in = 0; in < 4; in++)
                bf[in] = *(const float2*)(Bs + (kk * 16 + wn * 4 + in) * 64 + lane * 2);
#pragma unroll
            for (int im = 0; im < 4; im++)
#pragma unroll
                for (int in = 0; in < 4; in++)
                    mma_tf32(acc[im][in],
                             __float_as_uint(af[im].x), __float_as_uint(af[im].y),
                             __float_as_uint(af[im].z), __float_as_uint(af[im].w),
                             __float_as_uint(bf[in].x), __float_as_uint(bf[in].y));
        }
        __syncthreads();
    }

#pragma unroll
    for (int im = 0; im < 4; im++) {
        int r = row0 + wm * 64 + im * 16 + g;
#pragma unroll
        for (int in = 0; in < 4; in++) {
            int c = col0 + wn * 32 + in * 8 + tig * 2;
            float b0 = bias[c], b1 = bias[c + 1];
            float2 v0 = make_float2(acc[im][in][0] + b0, acc[im][in][1] + b1);
            float2 v1 = make_float2(acc[im][in][2] + b0, acc[im][in][3] + b1);
            *(float2*)&C[(size_t)r * N + c] = v0;
            *(float2*)&C[(size_t)(r + 8) * N + c] = v1;
        }
    }
}

// ---------------------------------------------------------------------------
// RoPE + scatter + splits + V transpose (unchanged)
// ---------------------------------------------------------------------------
__global__ __launch_bounds__(256)
void rope_scatter_split_kernel(const float* __restrict__ qkv,
                               const float2* __restrict__ rope,
                               __nv_bfloat16* __restrict__ qh,
                               __nv_bfloat16* __restrict__ ql,
                               __nv_bfloat16* __restrict__ kh,
                               __nv_bfloat16* __restrict__ kl,
                               __nv_bfloat16* __restrict__ vth,
                               __nv_bfloat16* __restrict__ vtl) {
    __shared__ __nv_bfloat16 vsh[64][66];
    __shared__ __nv_bfloat16 vsl[64][66];

    int bh = blockIdx.y;
    int tb = blockIdx.x * 64;
    int b = bh >> 4;
    int h = bh & 15;
    int tid = threadIdx.x;

    const float SCL = 0.125f * 1.4426950408889634f;

#pragma unroll
    for (int e = 0; e < 16; e++) {
        int idx = tid + e * 256;
        int tl = idx >> 6;
        int d = idx & 63;
        int t = tb + tl;
        size_t base = (size_t)(b * TSEQ + t) * QKVCOLS + h * DHEAD;
        float2 cs = rope[t * 32 + (d & 31)];

        float qv = qkv[base + d];
        float kv = qkv[base + CDIM + d];
        float vv = qkv[base + 2 * CDIM + d];
        int dp = (d < 32) ? d + 32 : d - 32;
        float sgn = (d < 32) ? -1.0f : 1.0f;
        float qr = qkv[base + dp];
        float kr = qkv[base + CDIM + dp];

        float qrot = (qv * cs.x + sgn * qr * cs.y) * SCL;
        float krot = kv * cs.x + sgn * kr * cs.y;

        size_t o = ((size_t)bh * TSEQ + t) * DHEAD + d;
        __nv_bfloat16 qhv = __float2bfloat16(qrot);
        __nv_bfloat16 khv = __float2bfloat16(krot);
        qh[o] = qhv;
        ql[o] = __float2bfloat16(qrot - __bfloat162float(qhv));
        kh[o] = khv;
        kl[o] = __float2bfloat16(krot - __bfloat162float(khv));

        __nv_bfloat16 vhv = __float2bfloat16(vv);
        vsh[d][tl] = vhv;
        vsl[d][tl] = __float2bfloat16(vv - __bfloat162float(vhv));
    }
    __syncthreads();
#pragma unroll
    for (int e = 0; e < 16; e++) {
        int idx = tid + e * 256;
        int d = idx >> 6;
        int tl = idx & 63;
        size_t o = ((size_t)bh * DHEAD + d) * TSEQ + tb + tl;
        vth[o] = vsh[d][tl];
        vtl[o] = vsl[d][tl];
    }
}

// ---------------------------------------------------------------------------
// Flash attention v4: ldmatrix fragment loads (bit-identical math to v3).
// ---------------------------------------------------------------------------
#define FRS 144
#define OFF_KH 0
#define OFF_KL 9216
#define OFF_VTH 18432
#define OFF_VTL 27648
#define BUFB 36864
#define FLASH_SMEM_BYTES (2 * BUFB)

#define NEGBIG (-1e30f)

__global__ __launch_bounds__(128, 3)
void flash_mma_kernel(const __nv_bfloat16* __restrict__ QH,
                      const __nv_bfloat16* __restrict__ QL,
                      const __nv_bfloat16* __restrict__ KH,
                      const __nv_bfloat16* __restrict__ KL,
                      const __nv_bfloat16* __restrict__ VTH,
                      const __nv_bfloat16* __restrict__ VTL) {
    extern __shared__ char smc[];
    const uint32_t smb = smem_u32(smc);

    int bh = blockIdx.y;
    int qt = gridDim.x - 1 - blockIdx.x;
    int q0 = qt * 64;

    int tid = threadIdx.x;
    int lane = tid & 31;
    int w = tid >> 5;
    int g = lane >> 2;
    int tig = lane & 3;
    const int r0 = w * 16 + g;

    // ldmatrix per-lane row/column base:
    //  group m = lane>>3; matrices {m0,m1} = rows nb*8+j; {m2,m3} = rows (nb+1)*8+j
    //  m0,m2: +0 bytes (reg0); m1,m3: +16 bytes (reg1)
    const int jj = lane & 7;
    const uint32_t ldsm_base =
        (uint32_t)((jj + ((lane >> 4) & 1) * 8) * FRS + ((lane >> 3) & 1) * 16);

    const __nv_bfloat16* KHg = KH + (size_t)bh * TSEQ * DHEAD;
    const __nv_bfloat16* KLg = KL + (size_t)bh * TSEQ * DHEAD;
    const __nv_bfloat16* VTHg = VTH + (size_t)bh * DHEAD * TSEQ;
    const __nv_bfloat16* VTLg = VTL + (size_t)bh * DHEAD * TSEQ;

    {
#pragma unroll
        for (int s = 0; s < 4; s++) {
            int f = tid + s * 128;
            int r = f >> 3;
            int c = (f & 7) * 8;
            uint32_t ro = (uint32_t)(r * FRS + c * 2);
            cp16(smb + OFF_KH + ro, KHg + (size_t)r * DHEAD + c);
            cp16(smb + OFF_KL + ro, KLg + (size_t)r * DHEAD + c);
            cp16(smb + OFF_VTH + ro, VTHg + (size_t)r * TSEQ + c);
            cp16(smb + OFF_VTL + ro, VTLg + (size_t)r * TSEQ + c);
        }
        CP_COMMIT();
    }

    uint32_t qah[4][4], qal[4][4];
    {
        const __nv_bfloat16* Qhg = QH + ((size_t)bh * TSEQ + q0 + r0) * DHEAD;
        const __nv_bfloat16* Qlg = QL + ((size_t)bh * TSEQ + q0 + r0) * DHEAD;
#pragma unroll
        for (int ks = 0; ks < 4; ks++) {
            int c0 = ks * 16 + 2 * tig;
            qah[ks][0] = *(const uint32_t*)(Qhg + c0);
            qah[ks][1] = *(const uint32_t*)(Qhg + 8 * DHEAD + c0);
            qah[ks][2] = *(const uint32_t*)(Qhg + c0 + 8);
            qah[ks][3] = *(const uint32_t*)(Qhg + 8 * DHEAD + c0 + 8);
            qal[ks][0] = *(const uint32_t*)(Qlg + c0);
            qal[ks][1] = *(const uint32_t*)(Qlg + 8 * DHEAD + c0);
            qal[ks][2] = *(const uint32_t*)(Qlg + c0 + 8);
            qal[ks][3] = *(const uint32_t*)(Qlg + 8 * DHEAD + c0 + 8);
        }
    }

    float oacc[8][4];
#pragma unroll
    for (int db = 0; db < 8; db++)
#pragma unroll
        for (int r = 0; r < 4; r++) oacc[db][r] = 0.0f;
    float m0 = NEGBIG, m1 = NEGBIG, l0 = 0.0f, l1 = 0.0f;

    for (int jt = 0; jt <= qt; jt++) {
        CP_WAIT0();
        __syncthreads();

        if (jt < qt) {
            int k0n = (jt + 1) * 64;
            uint32_t nb_ = smb + ((jt + 1) & 1) * BUFB;
#pragma unroll
            for (int s = 0; s < 4; s++) {
                int f = tid + s * 128;
                int r = f >> 3;
                int c = (f & 7) * 8;
                uint32_t ro = (uint32_t)(r * FRS + c * 2);
                cp16(nb_ + OFF_KH + ro, KHg + (size_t)(k0n + r) * DHEAD + c);
                cp16(nb_ + OFF_KL + ro, KLg + (size_t)(k0n + r) * DHEAD + c);
                cp16(nb_ + OFF_VTH + ro, VTHg + (size_t)r * TSEQ + k0n + c);
                cp16(nb_ + OFF_VTL + ro, VTLg + (size_t)r * TSEQ + k0n + c);
            }
            CP_COMMIT();
        }

        const uint32_t bufa = smb + (jt & 1) * BUFB + ldsm_base;

        // ---- S = Q K^T (bf16 split, fragments via ldmatrix.x4) ----
        float sacc[8][4];
#pragma unroll
        for (int nb = 0; nb < 8; nb++)
#pragma unroll
            for (int r = 0; r < 4; r++) sacc[nb][r] = 0.0f;

#pragma unroll
        for (int ks = 0; ks < 4; ks++) {
            const uint32_t ko = (uint32_t)(ks * 32);
#pragma unroll
            for (int nbp = 0; nbp < 4; nbp++) {
                const uint32_t ba = bufa + (uint32_t)(nbp * 16 * FRS) + ko;
                uint32_t h0, h1, h2, h3, e0, e1, e2, e3;
                ldsm_x4(h0, h1, h2, h3, ba + OFF_KH);
                ldsm_x4(e0, e1, e2, e3, ba + OFF_KL);
                mma_bf16(sacc[2 * nbp], qah[ks][0], qah[ks][1], qah[ks][2], qah[ks][3], h0, h1);
                mma_bf16(sacc[2 * nbp], qah[ks][0], qah[ks][1], qah[ks][2], qah[ks][3], e0, e1);
                mma_bf16(sacc[2 * nbp], qal[ks][0], qal[ks][1], qal[ks][2], qal[ks][3], h0, h1);
                mma_bf16(sacc[2 * nbp + 1], qah[ks][0], qah[ks][1], qah[ks][2], qah[ks][3], h2, h3);
                mma_bf16(sacc[2 * nbp + 1], qah[ks][0], qah[ks][1], qah[ks][2], qah[ks][3], e2, e3);
                mma_bf16(sacc[2 * nbp + 1], qal[ks][0], qal[ks][1], qal[ks][2], qal[ks][3], h2, h3);
            }
        }

        // ---- causal mask (diagonal tile only) ----
        if (jt == qt) {
#pragma unroll
            for (int nb = 0; nb < 8; nb++) {
                int c0 = nb * 8 + 2 * tig;
#pragma unroll
                for (int e = 0; e < 2; e++) {
                    if (c0 + e > r0) sacc[nb][e] = NEGBIG;
                    if (c0 + e > r0 + 8) sacc[nb][2 + e] = NEGBIG;
                }
            }
        }

        // ---- online softmax (log2 domain) ----
        float tm0 = NEGBIG, tm1 = NEGBIG;
#pragma unroll
        for (int nb = 0; nb < 8; nb++) {
            tm0 = fmaxf(tm0, fmaxf(sacc[nb][0], sacc[nb][1]));
            tm1 = fmaxf(tm1, fmaxf(sacc[nb][2], sacc[nb][3]));
        }
        tm0 = fmaxf(tm0, __shfl_xor_sync(0xffffffffu, tm0, 1));
        tm0 = fmaxf(tm0, __shfl_xor_sync(0xffffffffu, tm0, 2));
        tm1 = fmaxf(tm1, __shfl_xor_sync(0xffffffffu, tm1, 1));
        tm1 = fmaxf(tm1, __shfl_xor_sync(0xffffffffu, tm1, 2));

        float mn0 = fmaxf(m0, tm0);
        float mn1 = fmaxf(m1, tm1);
        float corr0 = ex2f(m0 - mn0);
        float corr1 = ex2f(m1 - mn1);
        float rs0 = 0.0f, rs1 = 0.0f;
#pragma unroll
        for (int nb = 0; nb < 8; nb++) {
            sacc[nb][0] = ex2f(sacc[nb][0] - mn0);
            sacc[nb][1] = ex2f(sacc[nb][1] - mn0);
            sacc[nb][2] = ex2f(sacc[nb][2] - mn1);
            sacc[nb][3] = ex2f(sacc[nb][3] - mn1);
            rs0 += sacc[nb][0] + sacc[nb][1];
            rs1 += sacc[nb][2] + sacc[nb][3];
        }
        rs0 += __shfl_xor_sync(0xffffffffu, rs0, 1);
        rs0 += __shfl_xor_sync(0xffffffffu, rs0, 2);
        rs1 += __shfl_xor_sync(0xffffffffu, rs1, 1);
        rs1 += __shfl_xor_sync(0xffffffffu, rs1, 2);

        l0 = l0 * corr0 + rs0;
        l1 = l1 * corr1 + rs1;
        m0 = mn0;
        m1 = mn1;
#pragma unroll
        for (int db = 0; db < 8; db++) {
            oacc[db][0] *= corr0;
            oacc[db][1] *= corr0;
            oacc[db][2] *= corr1;
            oacc[db][3] *= corr1;
        }

        // ---- O += P @ V (bf16 split, V fragments via ldmatrix.x4) ----
#pragma unroll
        for (int ks = 0; ks < 4; ks++) {
            uint32_t ph[4], pl[4];
            packsplit2(sacc[2 * ks][0], sacc[2 * ks][1], ph[0], pl[0]);
            packsplit2(sacc[2 * ks][2], sacc[2 * ks][3], ph[1], pl[1]);
            packsplit2(sacc[2 * ks + 1][0], sacc[2 * ks + 1][1], ph[2], pl[2]);
            packsplit2(sacc[2 * ks + 1][2], sacc[2 * ks + 1][3], ph[3], pl[3]);
            const uint32_t ko = (uint32_t)(ks * 32);
#pragma unroll
            for (int dbp = 0; dbp < 4; dbp++) {
                const uint32_t ba = bufa + (uint32_t)(dbp * 16 * FRS) + ko;
                uint32_t h0, h1, h2, h3, e0, e1, e2, e3;
                ldsm_x4(h0, h1, h2, h3, ba + OFF_VTH);
                ldsm_x4(e0, e1, e2, e3, ba + OFF_VTL);
                mma_bf16(oacc[2 * dbp], ph[0], ph[1], ph[2], ph[3], h0, h1);
                mma_bf16(oacc[2 * dbp], ph[0], ph[1], ph[2], ph[3], e0, e1);
                mma_bf16(oacc[2 * dbp], pl[0], pl[1], pl[2], pl[3], h0, h1);
                mma_bf16(oacc[2 * dbp + 1], ph[0], ph[1], ph[2], ph[3], h2, h3);
                mma_bf16(oacc[2 * dbp + 1], ph[0], ph[1], ph[2], ph[3], e2, e3);
                mma_bf16(oacc[2 * dbp + 1], pl[0], pl[1], pl[2], pl[3], h2, h3);
            }
        }
    }

    float inv0 = 1.0f / l0;
    float inv1 = 1.0f / l1;
    int b = bh >> 4;
    int h = bh & 15;
    int t0 = q0 + r0;
    int t1 = t0 + 8;
#pragma unroll
    for (int db = 0; db < 8; db++) {
        int col = h * 64 + db * 8 + 2 * tig;
        float2 y0 = make_float2(oacc[db][0] * inv0, oacc[db][1] * inv0);
        float2 y1 = make_float2(oacc[db][2] * inv1, oacc[db][3] * inv1);
        *(float2*)&g_y[(size_t)(b * TSEQ + t0) * CDIM + col] = y0;
        *(float2*)&g_y[(size_t)(b * TSEQ + t1) * CDIM + col] = y1;
    }
}

// ---------------------------------------------------------------------------
// Launch
// ---------------------------------------------------------------------------
extern "C" void kernel_launch(void* const* d_in, const int* in_sizes, int n_in,
                              void* d_out, int out_size) {
    const float* x      = (const float*)d_in[0];
    const float* w_attn = (const float*)d_in[1];
    const float* b_attn = (const float*)d_in[2];
    const float* w_proj = (const float*)d_in[3];
    const float* b_proj = (const float*)d_in[4];
    float* out = (float*)d_out;

    float *qkv, *y, *xf, *waf, *wpf, *yf;
    float2* rope;
    __nv_bfloat16 *qh, *ql, *kh, *kl, *vth, *vtl;
    cudaGetSymbolAddress((void**)&qkv, g_qkv);
    cudaGetSymbolAddress((void**)&xf, g_xf);
    cudaGetSymbolAddress((void**)&waf, g_waf);
    cudaGetSymbolAddress((void**)&wpf, g_wpf);
    cudaGetSymbolAddress((void**)&yf, g_yf);
    cudaGetSymbolAddress((void**)&qh, g_qh);
    cudaGetSymbolAddress((void**)&ql, g_ql);
    cudaGetSymbolAddress((void**)&kh, g_kh);
    cudaGetSymbolAddress((void**)&kl, g_kl);
    cudaGetSymbolAddress((void**)&vth, g_vth);
    cudaGetSymbolAddress((void**)&vtl, g_vtl);
    cudaGetSymbolAddress((void**)&y, g_y);
    cudaGetSymbolAddress((void**)&rope, g_rope);

    cudaFuncSetAttribute(gemm_tf32_kernel,
                         cudaFuncAttributeMaxDynamicSharedMemorySize,
                         GEMM_SMEM_BYTES);
    cudaFuncSetAttribute(flash_mma_kernel,
                         cudaFuncAttributeMaxDynamicSharedMemorySize,
                         FLASH_SMEM_BYTES);

    build_rope_kernel<<<(TSEQ * 32 + 255) / 256, 256>>>(rope);

    afrag_kernel<<<(MROWS / 16) * (CDIM / 8) * 32 / 256, 256>>>(x, xf, CDIM);
    bfrag_kernel<<<(CDIM / 8) * (QKVCOLS / 8) * 32 / 256, 256>>>(w_attn, waf, QKVCOLS);
    bfrag_kernel<<<(CDIM / 8) * (CDIM / 8) * 32 / 256, 256>>>(w_proj, wpf, CDIM);

    gemm_tf32_kernel<<<dim3(QKVCOLS / 128, MROWS / 128), 256, GEMM_SMEM_BYTES>>>(
        xf, waf, b_attn, qkv, MROWS, QKVCOLS, CDIM);

    rope_scatter_split_kernel<<<dim3(TSEQ / 64, BSZ * NHEAD), 256>>>(
        qkv, rope, qh, ql, kh, kl, vth, vtl);

    flash_mma_kernel<<<dim3(TSEQ / 64, BSZ * NHEAD), 128, FLASH_SMEM_BYTES>>>(
        qh, ql, kh, kl, vth, vtl);

    afrag_kernel<<<(MROWS / 16) * (CDIM / 8) * 32 / 256, 256>>>(y, yf, CDIM);
    gemm_tf32_kernel<<<dim3(CDIM / 128, MROWS / 128), 256, GEMM_SMEM_BYTES>>>(
        yf, wpf, b_proj, out, MROWS, CDIM, CDIM);
}